// round 11
// baseline (speedup 1.0000x reference)
#include <cuda_runtime.h>
#include <cuda_bf16.h>
#include <math.h>
#include <stdint.h>

#define SEQ 4096
#define DIM 1024
#define RMS_EPS 1.1920929e-7f  // jnp.finfo(float32).eps

// ======================= device scratch (alloc-free rule) =======================
#define AL __device__ __align__(16)
AL __nv_bfloat16 g_h_hi[SEQ * DIM],  g_h_lo[SEQ * DIM];
AL __nv_bfloat16 g_wq_hi[DIM * DIM], g_wq_lo[DIM * DIM];
AL __nv_bfloat16 g_wk_hi[DIM * DIM], g_wk_lo[DIM * DIM];
AL __nv_bfloat16 g_wv_hi[DIM * DIM], g_wv_lo[DIM * DIM];
AL __nv_bfloat16 g_q_hi[SEQ * DIM],  g_q_lo[SEQ * DIM];
AL __nv_bfloat16 g_k_hi[SEQ * DIM],  g_k_lo[SEQ * DIM];
AL __nv_bfloat16 g_vt_hi[DIM * SEQ], g_vt_lo[DIM * SEQ];   // V^T [DIM, SEQ]
AL float         g_logits[(size_t)SEQ * SEQ];
AL __nv_bfloat16 g_p_hi[(size_t)SEQ * SEQ], g_p_lo[(size_t)SEQ * SEQ];

// ======================= PTX helpers (base sm_103 target — no 'a' features) ==========
__device__ __forceinline__ uint32_t smem_u32(const void* p) {
    uint32_t a;
    asm("{ .reg .u64 t; cvta.to.shared.u64 t, %1; cvt.u32.u64 %0, t; }" : "=r"(a) : "l"(p));
    return a;
}
__device__ __forceinline__ void cp16(uint32_t dst, const void* src) {
    asm volatile("cp.async.cg.shared.global [%0], [%1], 16;" :: "r"(dst), "l"(src));
}
#define CP_COMMIT() asm volatile("cp.async.commit_group;" ::: "memory")
#define CP_WAIT1()  asm volatile("cp.async.wait_group 1;" ::: "memory")

__device__ __forceinline__ void ldsm_x4(uint32_t* r, uint32_t addr) {
    asm volatile("ldmatrix.sync.aligned.m8n8.x4.shared.b16 {%0,%1,%2,%3}, [%4];"
        : "=r"(r[0]), "=r"(r[1]), "=r"(r[2]), "=r"(r[3]) : "r"(addr) : "memory");
}
__device__ __forceinline__ void mma_bf16(float* c, const uint32_t* a, const uint32_t* b) {
    asm volatile(
        "mma.sync.aligned.m16n8k16.row.col.f32.bf16.bf16.f32 "
        "{%0,%1,%2,%3}, {%4,%5,%6,%7}, {%8,%9}, {%0,%1,%2,%3};"
        : "+f"(c[0]), "+f"(c[1]), "+f"(c[2]), "+f"(c[3])
        : "r"(a[0]), "r"(a[1]), "r"(a[2]), "r"(a[3]), "r"(b[0]), "r"(b[1]));
}

// ======================= split helper =======================
__device__ __forceinline__ void split1(float a, __nv_bfloat16& hi, __nv_bfloat16& lo) {
    hi = __float2bfloat16(a);
    lo = __float2bfloat16(a - __bfloat162float(hi));
}

// ======================= block reductions =======================
__device__ __forceinline__ float block_reduce_sum(float val) {
    __shared__ float sh[32];
    __syncthreads();
    int lane = threadIdx.x & 31, wid = threadIdx.x >> 5;
    #pragma unroll
    for (int o = 16; o > 0; o >>= 1) val += __shfl_down_sync(0xffffffffu, val, o);
    if (lane == 0) sh[wid] = val;
    __syncthreads();
    int nw = (blockDim.x + 31) >> 5;
    val = (threadIdx.x < nw) ? sh[threadIdx.x] : 0.0f;
    if (wid == 0) {
        #pragma unroll
        for (int o = 16; o > 0; o >>= 1) val += __shfl_down_sync(0xffffffffu, val, o);
        if (lane == 0) sh[0] = val;
    }
    __syncthreads();
    return sh[0];
}
__device__ __forceinline__ float block_reduce_max(float val) {
    __shared__ float sh[32];
    __syncthreads();
    int lane = threadIdx.x & 31, wid = threadIdx.x >> 5;
    #pragma unroll
    for (int o = 16; o > 0; o >>= 1) val = fmaxf(val, __shfl_down_sync(0xffffffffu, val, o));
    if (lane == 0) sh[wid] = val;
    __syncthreads();
    int nw = (blockDim.x + 31) >> 5;
    val = (threadIdx.x < nw) ? sh[threadIdx.x] : -INFINITY;
    if (wid == 0) {
        #pragma unroll
        for (int o = 16; o > 0; o >>= 1) val = fmaxf(val, __shfl_down_sync(0xffffffffu, val, o));
        if (lane == 0) sh[0] = val;
    }
    __syncthreads();
    return sh[0];
}

// ======================= embed + RMSNorm -> bf16 hi/lo =======================
__global__ void __launch_bounds__(256) embed_rmsnorm_kernel(
    const int* __restrict__ x, const float* __restrict__ emb,
    const float* __restrict__ norm_w,
    __nv_bfloat16* __restrict__ hhi, __nv_bfloat16* __restrict__ hlo)
{
    int s = blockIdx.x;
    int row = x[s];
    const float4* e4 = reinterpret_cast<const float4*>(emb + (size_t)row * DIM);
    const float4* w4 = reinterpret_cast<const float4*>(norm_w);

    float4 v = e4[threadIdx.x];
    float ss = v.x * v.x + v.y * v.y + v.z * v.z + v.w * v.w;
    ss = block_reduce_sum(ss);
    float scale = rsqrtf(ss * (1.0f / DIM) + RMS_EPS);
    float4 w = w4[threadIdx.x];
    float o[4];
    o[0] = v.x * scale * w.x; o[1] = v.y * scale * w.y;
    o[2] = v.z * scale * w.z; o[3] = v.w * scale * w.w;

    __nv_bfloat162* ph = reinterpret_cast<__nv_bfloat162*>(hhi + (size_t)s * DIM);
    __nv_bfloat162* pl = reinterpret_cast<__nv_bfloat162*>(hlo + (size_t)s * DIM);
    #pragma unroll
    for (int i = 0; i < 2; i++) {
        __nv_bfloat162 h2, l2;
        split1(o[2 * i],     h2.x, l2.x);
        split1(o[2 * i + 1], h2.y, l2.y);
        ph[threadIdx.x * 2 + i] = h2;
        pl[threadIdx.x * 2 + i] = l2;
    }
}

// ======================= f32 -> bf16 hi/lo elementwise =======================
__global__ void __launch_bounds__(256) split_kernel(
    const float4* __restrict__ src, __nv_bfloat162* __restrict__ hi,
    __nv_bfloat162* __restrict__ lo, int n4)
{
    int i = blockIdx.x * 256 + threadIdx.x;
    if (i >= n4) return;
    float4 v = src[i];
    __nv_bfloat162 h0, l0, h1, l1;
    split1(v.x, h0.x, l0.x); split1(v.y, h0.y, l0.y);
    split1(v.z, h1.x, l1.x); split1(v.w, h1.y, l1.y);
    hi[2 * i] = h0; hi[2 * i + 1] = h1;
    lo[2 * i] = l0; lo[2 * i + 1] = l1;
}

// ======================= softmax rows + split to bf16 hi/lo =======================
__global__ void __launch_bounds__(256) softmax_split(
    const float* __restrict__ logits,
    __nv_bfloat16* __restrict__ phi, __nv_bfloat16* __restrict__ plo)
{
    const float4* row = reinterpret_cast<const float4*>(logits + (size_t)blockIdx.x * SEQ);
    float4 v[4];
    float mx = -INFINITY;
    #pragma unroll
    for (int i = 0; i < 4; i++) {
        v[i] = row[threadIdx.x + i * 256];
        mx = fmaxf(mx, fmaxf(fmaxf(v[i].x, v[i].y), fmaxf(v[i].z, v[i].w)));
    }
    mx = block_reduce_max(mx);
    float sum = 0.0f;
    #pragma unroll
    for (int i = 0; i < 4; i++) {
        v[i].x = expf(v[i].x - mx); v[i].y = expf(v[i].y - mx);
        v[i].z = expf(v[i].z - mx); v[i].w = expf(v[i].w - mx);
        sum += v[i].x + v[i].y + v[i].z + v[i].w;
    }
    sum = block_reduce_sum(sum);
    float inv = 1.0f / sum;
    __nv_bfloat162* ph = reinterpret_cast<__nv_bfloat162*>(phi + (size_t)blockIdx.x * SEQ);
    __nv_bfloat162* pl = reinterpret_cast<__nv_bfloat162*>(plo + (size_t)blockIdx.x * SEQ);
    #pragma unroll
    for (int i = 0; i < 4; i++) {
        __nv_bfloat162 h0, l0, h1, l1;
        split1(v[i].x * inv, h0.x, l0.x); split1(v[i].y * inv, h0.y, l0.y);
        split1(v[i].z * inv, h1.x, l1.x); split1(v[i].w * inv, h1.y, l1.y);
        int f = threadIdx.x + i * 256;
        ph[2 * f] = h0; ph[2 * f + 1] = h1;
        pl[2 * f] = l0; pl[2 * f + 1] = l1;
    }
}

// ======================= shared GEMM core (mma.sync bf16-split) =======================
// CTA tile 256x128: acc += (Ahi+Alo)[256 rows @arow0, K] * ((Bhi+Blo)[128 rows @brow0, K])^T
// 256 threads, 8 warps in 4(m) x 2(n), warp tile 64x64. 3-stage cp.async pipeline.
#define A_TILE_BYTES 16384           // 256 rows x 64B
#define B_TILE_BYTES 8192            // 128 rows x 64B
#define STAGE_BYTES (2 * A_TILE_BYTES + 2 * B_TILE_BYTES)  // 48 KB
#define NSTAGE 3
#define GEMM_SMEM (NSTAGE * STAGE_BYTES)                   // 144 KB

#define OFF_AHI 0
#define OFF_ALO A_TILE_BYTES
#define OFF_BHI (2 * A_TILE_BYTES)
#define OFF_BLO (2 * A_TILE_BYTES + B_TILE_BYTES)

__device__ __forceinline__ uint32_t sw(uint32_t row, uint32_t chunk) {
    return row * 64u + ((chunk ^ ((row >> 1) & 3u)) << 4);
}

__device__ __forceinline__ void load_stage(uint32_t sbase,
    const __nv_bfloat16* __restrict__ Ahi, const __nv_bfloat16* __restrict__ Alo,
    const __nv_bfloat16* __restrict__ Bhi, const __nv_bfloat16* __restrict__ Blo,
    size_t arow0, size_t brow0, int K, int k0, int tid)
{
    // A: 256 rows, 4 float4-chunks per row -> 1024 loads per tile (4/thread)
    #pragma unroll
    for (int j = 0; j < 4; j++) {
        int idx = tid + j * 256;
        int row = idx >> 2, ch = idx & 3;
        uint32_t so = sw(row, ch);
        size_t goff = (size_t)row * K + k0 + ch * 8;
        cp16(sbase + OFF_AHI + so, Ahi + arow0 * K + goff);
        cp16(sbase + OFF_ALO + so, Alo + arow0 * K + goff);
    }
    // B: 128 rows -> 512 loads per tile (2/thread)
    #pragma unroll
    for (int j = 0; j < 2; j++) {
        int idx = tid + j * 256;
        int row = idx >> 2, ch = idx & 3;
        uint32_t so = sw(row, ch);
        size_t goff = (size_t)row * K + k0 + ch * 8;
        cp16(sbase + OFF_BHI + so, Bhi + brow0 * K + goff);
        cp16(sbase + OFF_BLO + so, Blo + brow0 * K + goff);
    }
}

__device__ __forceinline__ void gemm_core(uint32_t sbase,
    const __nv_bfloat16* __restrict__ Ahi, const __nv_bfloat16* __restrict__ Alo,
    const __nv_bfloat16* __restrict__ Bhi, const __nv_bfloat16* __restrict__ Blo,
    size_t arow0, size_t brow0, int K, float acc[4][8][4])
{
    const int tid = threadIdx.x, wid = tid >> 5, lid = tid & 31;
    const int wm = wid >> 1, wn = wid & 1;      // 4(m) x 2(n) warp grid, warp tile 64x64

    const int a_r  = (lid & 7) + ((lid >> 3) & 1) * 8;
    const int a_kb = lid >> 4;
    const int b_r  = (lid & 7) + (lid >> 4) * 8;
    const int b_kb = (lid >> 3) & 1;
    const int nch = K >> 5;

    load_stage(sbase, Ahi, Alo, Bhi, Blo, arow0, brow0, K, 0, tid);
    CP_COMMIT();
    load_stage(sbase + STAGE_BYTES, Ahi, Alo, Bhi, Blo, arow0, brow0, K, 32, tid);
    CP_COMMIT();

    int slot = 0, nslot = 2;
    for (int c = 0; c < nch; c++) {
        CP_WAIT1();
        __syncthreads();
        const uint32_t cur = sbase + (uint32_t)slot * STAGE_BYTES;
        if (c + 2 < nch)
            load_stage(sbase + (uint32_t)nslot * STAGE_BYTES,
                       Ahi, Alo, Bhi, Blo, arow0, brow0, K, (c + 2) * 32, tid);
        CP_COMMIT();   // always commit to keep wait_group 1 semantics
        slot = (slot == 2) ? 0 : slot + 1;
        nslot = (nslot == 2) ? 0 : nslot + 1;

        #pragma unroll
        for (int ks = 0; ks < 2; ks++) {
            uint32_t ahi[4][4], alo[4][4];
            #pragma unroll
            for (int mf = 0; mf < 4; mf++) {
                uint32_t arow = (uint32_t)(wm * 64 + mf * 16 + a_r);
                uint32_t ach  = (uint32_t)(ks * 2 + a_kb);
                ldsm_x4(ahi[mf], cur + OFF_AHI + sw(arow, ach));
                ldsm_x4(alo[mf], cur + OFF_ALO + sw(arow, ach));
            }
            #pragma unroll
            for (int np = 0; np < 4; np++) {   // 2 n-frags per np block
                uint32_t brow = (uint32_t)(wn * 64 + np * 16 + b_r);
                uint32_t bch  = (uint32_t)(ks * 2 + b_kb);
                uint32_t th[4], tl[4];
                ldsm_x4(th, cur + OFF_BHI + sw(brow, bch));
                ldsm_x4(tl, cur + OFF_BLO + sw(brow, bch));
                uint32_t b0h[2] = { th[0], th[1] }, b1h[2] = { th[2], th[3] };
                uint32_t b0l[2] = { tl[0], tl[1] }, b1l[2] = { tl[2], tl[3] };
                // three dependency-spread passes
                #pragma unroll
                for (int mf = 0; mf < 4; mf++) {
                    mma_bf16(acc[mf][np * 2],     ahi[mf], b0h);
                    mma_bf16(acc[mf][np * 2 + 1], ahi[mf], b1h);
                }
                #pragma unroll
                for (int mf = 0; mf < 4; mf++) {
                    mma_bf16(acc[mf][np * 2],     ahi[mf], b0l);
                    mma_bf16(acc[mf][np * 2 + 1], ahi[mf], b1l);
                }
                #pragma unroll
                for (int mf = 0; mf < 4; mf++) {
                    mma_bf16(acc[mf][np * 2],     alo[mf], b0h);
                    mma_bf16(acc[mf][np * 2 + 1], alo[mf], b1h);
                }
            }
        }
    }
    __syncthreads();
}

// ======================= QKV fused kernel =======================
// grid (24, 16): bx 0..7 -> Q, 8..15 -> K, 16..23 -> V (transposed into V^T)
__global__ void __launch_bounds__(256, 1) qkv_kernel(
    const __nv_bfloat16* __restrict__ hhi, const __nv_bfloat16* __restrict__ hlo,
    const __nv_bfloat16* __restrict__ wqh, const __nv_bfloat16* __restrict__ wql,
    const __nv_bfloat16* __restrict__ wkh, const __nv_bfloat16* __restrict__ wkl,
    const __nv_bfloat16* __restrict__ wvh, const __nv_bfloat16* __restrict__ wvl,
    __nv_bfloat16* __restrict__ qh, __nv_bfloat16* __restrict__ ql,
    __nv_bfloat16* __restrict__ kh, __nv_bfloat16* __restrict__ kl,
    __nv_bfloat16* __restrict__ vth, __nv_bfloat16* __restrict__ vtl)
{
    extern __shared__ char smem[];
    const uint32_t sbase = smem_u32(smem);
    const int which = blockIdx.x >> 3;          // 0=Q, 1=K, 2=V
    const int bxx = blockIdx.x & 7;

    const __nv_bfloat16* Bh = (which == 0) ? wqh : (which == 1) ? wkh : wvh;
    const __nv_bfloat16* Bl = (which == 0) ? wql : (which == 1) ? wkl : wvl;

    const size_t arow0 = (size_t)blockIdx.y * 256;
    const size_t brow0 = (size_t)bxx * 128;

    float acc[4][8][4] = {};
    gemm_core(sbase, hhi, hlo, Bh, Bl, arow0, brow0, DIM, acc);

    const int wid = threadIdx.x >> 5, lid = threadIdx.x & 31;
    const int wm = wid >> 1, wn = wid & 1;
    const int rbase = (int)arow0 + wm * 64 + (lid >> 2);
    const int cbase = (int)brow0 + wn * 64 + (lid & 3) * 2;

    if (which < 2) {
        __nv_bfloat16* Chi = (which == 0) ? qh : kh;
        __nv_bfloat16* Clo = (which == 0) ? ql : kl;
        #pragma unroll
        for (int mf = 0; mf < 4; mf++)
            #pragma unroll
            for (int nf = 0; nf < 8; nf++)
                #pragma unroll
                for (int half = 0; half < 2; half++) {
                    size_t r = (size_t)(rbase + mf * 16 + half * 8);
                    size_t cc = (size_t)(cbase + nf * 8);
                    __nv_bfloat162 hv, lv;
                    split1(acc[mf][nf][half * 2],     hv.x, lv.x);
                    split1(acc[mf][nf][half * 2 + 1], hv.y, lv.y);
                    *reinterpret_cast<__nv_bfloat162*>(Chi + r * DIM + cc) = hv;
                    *reinterpret_cast<__nv_bfloat162*>(Clo + r * DIM + cc) = lv;
                }
    } else {
        // V: write transposed -> vt[c][r]
        #pragma unroll
        for (int mf = 0; mf < 4; mf++)
            #pragma unroll
            for (int nf = 0; nf < 8; nf++)
                #pragma unroll
                for (int half = 0; half < 2; half++) {
                    size_t r = (size_t)(rbase + mf * 16 + half * 8);
                    size_t c0 = (size_t)(cbase + nf * 8);
                    float v0 = acc[mf][nf][half * 2];
                    float v1 = acc[mf][nf][half * 2 + 1];
                    __nv_bfloat16 h0, l0, h1, l1;
                    split1(v0, h0, l0);
                    split1(v1, h1, l1);
                    vth[c0 * SEQ + r] = h0;       vtl[c0 * SEQ + r] = l0;
                    vth[(c0 + 1) * SEQ + r] = h1; vtl[(c0 + 1) * SEQ + r] = l1;
                }
    }
}

// ======================= generic GEMM kernels (logits / PV) =======================
// MODE: 0 = f32 store, 2 = silu(f32) store
template <int MODE>
__global__ void __launch_bounds__(256, 1) gemm_bs(
    const __nv_bfloat16* __restrict__ Ahi, const __nv_bfloat16* __restrict__ Alo,
    const __nv_bfloat16* __restrict__ Bhi, const __nv_bfloat16* __restrict__ Blo,
    int K, int ldc, float* __restrict__ Cf)
{
    extern __shared__ char smem[];
    const uint32_t sbase = smem_u32(smem);
    const size_t arow0 = (size_t)blockIdx.y * 256;
    const size_t brow0 = (size_t)blockIdx.x * 128;

    float acc[4][8][4] = {};
    gemm_core(sbase, Ahi, Alo, Bhi, Blo, arow0, brow0, K, acc);

    const int wid = threadIdx.x >> 5, lid = threadIdx.x & 31;
    const int wm = wid >> 1, wn = wid & 1;
    const int rbase = (int)arow0 + wm * 64 + (lid >> 2);
    const int cbase = (int)brow0 + wn * 64 + (lid & 3) * 2;
    #pragma unroll
    for (int mf = 0; mf < 4; mf++)
        #pragma unroll
        for (int nf = 0; nf < 8; nf++)
            #pragma unroll
            for (int half = 0; half < 2; half++) {
                size_t r = (size_t)(rbase + mf * 16 + half * 8);
                size_t cc = (size_t)(cbase + nf * 8);
                float v0 = acc[mf][nf][half * 2];
                float v1 = acc[mf][nf][half * 2 + 1];
                if (MODE == 2) {
                    v0 = v0 / (1.0f + expf(-v0));
                    v1 = v1 / (1.0f + expf(-v1));
                }
                *reinterpret_cast<float2*>(Cf + r * ldc + cc) = make_float2(v0, v1);
            }
}

// ======================= host launch =======================
extern "C" void kernel_launch(void* const* d_in, const int* in_sizes, int n_in,
                              void* d_out, int out_size)
{
    const int*   x      = (const int*)  d_in[0];
    const float* emb    = (const float*)d_in[1];
    const float* norm_w = (const float*)d_in[2];
    const float* Wq     = (const float*)d_in[3];
    const float* Wk     = (const float*)d_in[4];
    const float* Wv     = (const float*)d_in[5];
    float* out = (float*)d_out;

    __nv_bfloat16 *h_hi, *h_lo, *wq_hi, *wq_lo, *wk_hi, *wk_lo, *wv_hi, *wv_lo;
    __nv_bfloat16 *q_hi, *q_lo, *k_hi, *k_lo, *vt_hi, *vt_lo, *p_hi, *p_lo;
    float *logits;
    cudaGetSymbolAddress((void**)&h_hi, g_h_hi);   cudaGetSymbolAddress((void**)&h_lo, g_h_lo);
    cudaGetSymbolAddress((void**)&wq_hi, g_wq_hi); cudaGetSymbolAddress((void**)&wq_lo, g_wq_lo);
    cudaGetSymbolAddress((void**)&wk_hi, g_wk_hi); cudaGetSymbolAddress((void**)&wk_lo, g_wk_lo);
    cudaGetSymbolAddress((void**)&wv_hi, g_wv_hi); cudaGetSymbolAddress((void**)&wv_lo, g_wv_lo);
    cudaGetSymbolAddress((void**)&q_hi, g_q_hi);   cudaGetSymbolAddress((void**)&q_lo, g_q_lo);
    cudaGetSymbolAddress((void**)&k_hi, g_k_hi);   cudaGetSymbolAddress((void**)&k_lo, g_k_lo);
    cudaGetSymbolAddress((void**)&vt_hi, g_vt_hi); cudaGetSymbolAddress((void**)&vt_lo, g_vt_lo);
    cudaGetSymbolAddress((void**)&p_hi, g_p_hi);   cudaGetSymbolAddress((void**)&p_lo, g_p_lo);
    cudaGetSymbolAddress((void**)&logits, g_logits);

    cudaFuncSetAttribute((const void*)qkv_kernel, cudaFuncAttributeMaxDynamicSharedMemorySize, GEMM_SMEM);
    cudaFuncSetAttribute((const void*)gemm_bs<0>, cudaFuncAttributeMaxDynamicSharedMemorySize, GEMM_SMEM);
    cudaFuncSetAttribute((const void*)gemm_bs<2>, cudaFuncAttributeMaxDynamicSharedMemorySize, GEMM_SMEM);

    // 1) embed + RMSNorm -> h hi/lo
    embed_rmsnorm_kernel<<<SEQ, 256>>>(x, emb, norm_w, h_hi, h_lo);

    // 2) split weights
    const int W4 = DIM * DIM / 4;
    split_kernel<<<W4 / 256, 256>>>((const float4*)Wq, (__nv_bfloat162*)wq_hi, (__nv_bfloat162*)wq_lo, W4);
    split_kernel<<<W4 / 256, 256>>>((const float4*)Wk, (__nv_bfloat162*)wk_hi, (__nv_bfloat162*)wk_lo, W4);
    split_kernel<<<W4 / 256, 256>>>((const float4*)Wv, (__nv_bfloat162*)wv_hi, (__nv_bfloat162*)wv_lo, W4);

    // 3) fused QKV projections (one launch; V written transposed+split)
    qkv_kernel<<<dim3(24, SEQ / 256), 256, GEMM_SMEM>>>(
        h_hi, h_lo, wq_hi, wq_lo, wk_hi, wk_lo, wv_hi, wv_lo,
        q_hi, q_lo, k_hi, k_lo, vt_hi, vt_lo);

    // 4) logits = q @ k^T
    dim3 gattn(SEQ / 128, SEQ / 256);
    gemm_bs<0><<<gattn, 256, GEMM_SMEM>>>(q_hi, q_lo, k_hi, k_lo, DIM, SEQ, logits);

    // 5) softmax + split -> p hi/lo
    softmax_split<<<SEQ, 256>>>(logits, p_hi, p_lo);

    // 6) out = silu(P @ V) = silu(P @ (V^T)^T)
    dim3 gout(DIM / 128, SEQ / 256);
    gemm_bs<2><<<gout, 256, GEMM_SMEM>>>(p_hi, p_lo, vt_hi, vt_lo, SEQ, DIM, out);
}

// round 14
// speedup vs baseline: 1.0894x; 1.0894x over previous
#include <cuda_runtime.h>
#include <cuda_bf16.h>
#include <math.h>
#include <stdint.h>

#define SEQ 4096
#define DIM 1024
#define RMS_EPS 1.1920929e-7f  // jnp.finfo(float32).eps

// ======================= device scratch (alloc-free rule) =======================
#define AL __device__ __align__(16)
AL __nv_bfloat16 g_h_hi[SEQ * DIM],  g_h_lo[SEQ * DIM];
AL __nv_bfloat16 g_wq_hi[DIM * DIM], g_wq_lo[DIM * DIM];
AL __nv_bfloat16 g_wk_hi[DIM * DIM], g_wk_lo[DIM * DIM];
AL __nv_bfloat16 g_wv_hi[DIM * DIM], g_wv_lo[DIM * DIM];
AL __nv_bfloat16 g_q_hi[SEQ * DIM],  g_q_lo[SEQ * DIM];
AL __nv_bfloat16 g_k_hi[SEQ * DIM],  g_k_lo[SEQ * DIM];
AL __nv_bfloat16 g_vt_hi[DIM * SEQ], g_vt_lo[DIM * SEQ];   // V^T [DIM, SEQ]
AL float         g_logits[(size_t)SEQ * SEQ];
AL __nv_bfloat16 g_p_hi[(size_t)SEQ * SEQ], g_p_lo[(size_t)SEQ * SEQ];

// ======================= PTX helpers (base sm_103 target — no 'a' features) ==========
__device__ __forceinline__ uint32_t smem_u32(const void* p) {
    uint32_t a;
    asm("{ .reg .u64 t; cvta.to.shared.u64 t, %1; cvt.u32.u64 %0, t; }" : "=r"(a) : "l"(p));
    return a;
}
__device__ __forceinline__ void cp16(uint32_t dst, const void* src) {
    asm volatile("cp.async.cg.shared.global [%0], [%1], 16;" :: "r"(dst), "l"(src));
}
#define CP_COMMIT() asm volatile("cp.async.commit_group;" ::: "memory")
#define CP_WAIT1()  asm volatile("cp.async.wait_group 1;" ::: "memory")

__device__ __forceinline__ void ldsm_x4(uint32_t* r, uint32_t addr) {
    asm volatile("ldmatrix.sync.aligned.m8n8.x4.shared.b16 {%0,%1,%2,%3}, [%4];"
        : "=r"(r[0]), "=r"(r[1]), "=r"(r[2]), "=r"(r[3]) : "r"(addr) : "memory");
}
__device__ __forceinline__ void mma_bf16(float* c, const uint32_t* a, const uint32_t* b) {
    asm volatile(
        "mma.sync.aligned.m16n8k16.row.col.f32.bf16.bf16.f32 "
        "{%0,%1,%2,%3}, {%4,%5,%6,%7}, {%8,%9}, {%0,%1,%2,%3};"
        : "+f"(c[0]), "+f"(c[1]), "+f"(c[2]), "+f"(c[3])
        : "r"(a[0]), "r"(a[1]), "r"(a[2]), "r"(a[3]), "r"(b[0]), "r"(b[1]));
}

// ======================= fast math (FMA-pipe, no MUFU) =======================
// e^x with ~1e-7 rel error: 2^(x*log2e), magic-number round, deg-6 poly, exponent add.
__device__ __forceinline__ float fast_exp(float x) {
    float t = x * 1.4426950408889634f;
    t = fmaxf(fminf(t, 125.0f), -125.0f);
    float r = t + 12582912.0f;                       // 2^23 + 2^22 (round to nearest int)
    int   n = __float_as_int(r) - 0x4B400000;
    float f = t - (r - 12582912.0f);                 // f in [-0.5, 0.5]
    float p = 1.5403530393381609e-4f;
    p = fmaf(p, f, 1.3333558146428443e-3f);
    p = fmaf(p, f, 9.6181291076284772e-3f);
    p = fmaf(p, f, 5.5504108664821580e-2f);
    p = fmaf(p, f, 2.4022650695910072e-1f);
    p = fmaf(p, f, 6.9314718055994531e-1f);
    p = fmaf(p, f, 1.0f);
    return __int_as_float(__float_as_int(p) + (n << 23));
}
// 1/y via bit-hack + 3 Newton iterations (no MUFU rcp)
__device__ __forceinline__ float fast_rcp(float y) {
    float r = __int_as_float(0x7EF311C3 - __float_as_int(y));
    r = r * (2.0f - y * r);
    r = r * (2.0f - y * r);
    r = r * (2.0f - y * r);
    return r;
}
__device__ __forceinline__ float fast_silu(float v) {
    float e = fast_exp(-v);
    return v * fast_rcp(1.0f + e);
}

// ======================= split helper =======================
__device__ __forceinline__ void split1(float a, __nv_bfloat16& hi, __nv_bfloat16& lo) {
    hi = __float2bfloat16(a);
    lo = __float2bfloat16(a - __bfloat162float(hi));
}

// ======================= block reductions =======================
__device__ __forceinline__ float block_reduce_sum(float val) {
    __shared__ float sh[32];
    __syncthreads();
    int lane = threadIdx.x & 31, wid = threadIdx.x >> 5;
    #pragma unroll
    for (int o = 16; o > 0; o >>= 1) val += __shfl_down_sync(0xffffffffu, val, o);
    if (lane == 0) sh[wid] = val;
    __syncthreads();
    int nw = (blockDim.x + 31) >> 5;
    val = (threadIdx.x < nw) ? sh[threadIdx.x] : 0.0f;
    if (wid == 0) {
        #pragma unroll
        for (int o = 16; o > 0; o >>= 1) val += __shfl_down_sync(0xffffffffu, val, o);
        if (lane == 0) sh[0] = val;
    }
    __syncthreads();
    return sh[0];
}
__device__ __forceinline__ float block_reduce_max(float val) {
    __shared__ float sh[32];
    __syncthreads();
    int lane = threadIdx.x & 31, wid = threadIdx.x >> 5;
    #pragma unroll
    for (int o = 16; o > 0; o >>= 1) val = fmaxf(val, __shfl_down_sync(0xffffffffu, val, o));
    if (lane == 0) sh[wid] = val;
    __syncthreads();
    int nw = (blockDim.x + 31) >> 5;
    val = (threadIdx.x < nw) ? sh[threadIdx.x] : -INFINITY;
    if (wid == 0) {
        #pragma unroll
        for (int o = 16; o > 0; o >>= 1) val = fmaxf(val, __shfl_down_sync(0xffffffffu, val, o));
        if (lane == 0) sh[0] = val;
    }
    __syncthreads();
    return sh[0];
}

// ======================= embed + RMSNorm -> bf16 hi/lo =======================
__global__ void __launch_bounds__(256) embed_rmsnorm_kernel(
    const int* __restrict__ x, const float* __restrict__ emb,
    const float* __restrict__ norm_w,
    __nv_bfloat16* __restrict__ hhi, __nv_bfloat16* __restrict__ hlo)
{
    int s = blockIdx.x;
    int row = x[s];
    const float4* e4 = reinterpret_cast<const float4*>(emb + (size_t)row * DIM);
    const float4* w4 = reinterpret_cast<const float4*>(norm_w);

    float4 v = e4[threadIdx.x];
    float ss = v.x * v.x + v.y * v.y + v.z * v.z + v.w * v.w;
    ss = block_reduce_sum(ss);
    float scale = rsqrtf(ss * (1.0f / DIM) + RMS_EPS);
    float4 w = w4[threadIdx.x];
    float o[4];
    o[0] = v.x * scale * w.x; o[1] = v.y * scale * w.y;
    o[2] = v.z * scale * w.z; o[3] = v.w * scale * w.w;

    __nv_bfloat162* ph = reinterpret_cast<__nv_bfloat162*>(hhi + (size_t)s * DIM);
    __nv_bfloat162* pl = reinterpret_cast<__nv_bfloat162*>(hlo + (size_t)s * DIM);
    #pragma unroll
    for (int i = 0; i < 2; i++) {
        __nv_bfloat162 h2, l2;
        split1(o[2 * i],     h2.x, l2.x);
        split1(o[2 * i + 1], h2.y, l2.y);
        ph[threadIdx.x * 2 + i] = h2;
        pl[threadIdx.x * 2 + i] = l2;
    }
}

// ======================= f32 -> bf16 hi/lo: all three weights in one launch ============
__global__ void __launch_bounds__(256) split3_kernel(
    const float4* __restrict__ sa, const float4* __restrict__ sb, const float4* __restrict__ sc,
    __nv_bfloat162* __restrict__ ah, __nv_bfloat162* __restrict__ al,
    __nv_bfloat162* __restrict__ bh, __nv_bfloat162* __restrict__ bl,
    __nv_bfloat162* __restrict__ ch, __nv_bfloat162* __restrict__ cl, int n4)
{
    int which = blockIdx.x / ((n4 + 255) / 256);
    int i = (blockIdx.x % ((n4 + 255) / 256)) * 256 + threadIdx.x;
    if (i >= n4) return;
    const float4* src = (which == 0) ? sa : (which == 1) ? sb : sc;
    __nv_bfloat162* hi = (which == 0) ? ah : (which == 1) ? bh : ch;
    __nv_bfloat162* lo = (which == 0) ? al : (which == 1) ? bl : cl;
    float4 v = src[i];
    __nv_bfloat162 h0, l0, h1, l1;
    split1(v.x, h0.x, l0.x); split1(v.y, h0.y, l0.y);
    split1(v.z, h1.x, l1.x); split1(v.w, h1.y, l1.y);
    hi[2 * i] = h0; hi[2 * i + 1] = h1;
    lo[2 * i] = l0; lo[2 * i + 1] = l1;
}

// ======================= softmax rows + split to bf16 hi/lo (FMA-pipe exp) ==========
__global__ void __launch_bounds__(256) softmax_split(
    const float* __restrict__ logits,
    __nv_bfloat16* __restrict__ phi, __nv_bfloat16* __restrict__ plo)
{
    const float4* row = reinterpret_cast<const float4*>(logits + (size_t)blockIdx.x * SEQ);
    float4 v[4];
    float mx = -INFINITY;
    #pragma unroll
    for (int i = 0; i < 4; i++) {
        v[i] = row[threadIdx.x + i * 256];
        mx = fmaxf(mx, fmaxf(fmaxf(v[i].x, v[i].y), fmaxf(v[i].z, v[i].w)));
    }
    mx = block_reduce_max(mx);
    float sum = 0.0f;
    #pragma unroll
    for (int i = 0; i < 4; i++) {
        v[i].x = fast_exp(v[i].x - mx); v[i].y = fast_exp(v[i].y - mx);
        v[i].z = fast_exp(v[i].z - mx); v[i].w = fast_exp(v[i].w - mx);
        sum += v[i].x + v[i].y + v[i].z + v[i].w;
    }
    sum = block_reduce_sum(sum);
    float inv = fast_rcp(sum);
    __nv_bfloat162* ph = reinterpret_cast<__nv_bfloat162*>(phi + (size_t)blockIdx.x * SEQ);
    __nv_bfloat162* pl = reinterpret_cast<__nv_bfloat162*>(plo + (size_t)blockIdx.x * SEQ);
    #pragma unroll
    for (int i = 0; i < 4; i++) {
        __nv_bfloat162 h0, l0, h1, l1;
        split1(v[i].x * inv, h0.x, l0.x); split1(v[i].y * inv, h0.y, l0.y);
        split1(v[i].z * inv, h1.x, l1.x); split1(v[i].w * inv, h1.y, l1.y);
        int f = threadIdx.x + i * 256;
        ph[2 * f] = h0; ph[2 * f + 1] = h1;
        pl[2 * f] = l0; pl[2 * f + 1] = l1;
    }
}

// ======================= shared GEMM core (mma.sync bf16-split) — R7 config ==========
// 128x128 CTA tile, 128 threads, 4 warps in 2x2, warp tile 64x64, 3-stage pipeline.
#define TILE_BYTES 8192              // 128 rows x 64B (32 bf16)
#define STAGE_BYTES (4 * TILE_BYTES) // Ahi, Alo, Bhi, Blo
#define NSTAGE 3
#define GEMM_SMEM (NSTAGE * STAGE_BYTES)

__device__ __forceinline__ uint32_t sw(uint32_t row, uint32_t chunk) {
    return row * 64u + ((chunk ^ ((row >> 1) & 3u)) << 4);
}

__device__ __forceinline__ void load_stage(uint32_t sbase,
    const __nv_bfloat16* __restrict__ Ahi, const __nv_bfloat16* __restrict__ Alo,
    const __nv_bfloat16* __restrict__ Bhi, const __nv_bfloat16* __restrict__ Blo,
    size_t arow0, size_t brow0, int K, int k0, int tid)
{
    #pragma unroll
    for (int j = 0; j < 4; j++) {
        int idx = tid + j * 128;
        int row = idx >> 2, ch = idx & 3;
        uint32_t so = sw(row, ch);
        size_t goff = (size_t)row * K + k0 + ch * 8;   // bf16 elements
        cp16(sbase + 0 * TILE_BYTES + so, Ahi + arow0 * K + goff);
        cp16(sbase + 1 * TILE_BYTES + so, Alo + arow0 * K + goff);
        cp16(sbase + 2 * TILE_BYTES + so, Bhi + brow0 * K + goff);
        cp16(sbase + 3 * TILE_BYTES + so, Blo + brow0 * K + goff);
    }
}

__device__ __forceinline__ void gemm_core(uint32_t sbase,
    const __nv_bfloat16* __restrict__ Ahi, const __nv_bfloat16* __restrict__ Alo,
    const __nv_bfloat16* __restrict__ Bhi, const __nv_bfloat16* __restrict__ Blo,
    size_t arow0, size_t brow0, int K, float acc[4][8][4])
{
    const int tid = threadIdx.x, wid = tid >> 5, lid = tid & 31;
    const int wm = wid >> 1, wn = wid & 1;      // 2 x 2 warp grid, warp tile 64x64

    const int a_r  = (lid & 7) + ((lid >> 3) & 1) * 8;
    const int a_kb = lid >> 4;
    const int b_r  = (lid & 7) + (lid >> 4) * 8;
    const int b_kb = (lid >> 3) & 1;
    const int nch = K >> 5;

    load_stage(sbase, Ahi, Alo, Bhi, Blo, arow0, brow0, K, 0, tid);
    CP_COMMIT();
    load_stage(sbase + STAGE_BYTES, Ahi, Alo, Bhi, Blo, arow0, brow0, K, 32, tid);
    CP_COMMIT();

    int slot = 0, nslot = 2;
    for (int c = 0; c < nch; c++) {
        CP_WAIT1();
        __syncthreads();
        const uint32_t cur = sbase + (uint32_t)slot * STAGE_BYTES;
        if (c + 2 < nch)
            load_stage(sbase + (uint32_t)nslot * STAGE_BYTES,
                       Ahi, Alo, Bhi, Blo, arow0, brow0, K, (c + 2) * 32, tid);
        CP_COMMIT();   // always commit (possibly empty group) to keep wait_group 1 semantics
        slot = (slot == 2) ? 0 : slot + 1;
        nslot = (nslot == 2) ? 0 : nslot + 1;

        #pragma unroll
        for (int ks = 0; ks < 2; ks++) {
            uint32_t ahi[4][4], alo[4][4];
            #pragma unroll
            for (int mf = 0; mf < 4; mf++) {
                uint32_t arow = (uint32_t)(wm * 64 + mf * 16 + a_r);
                uint32_t ach  = (uint32_t)(ks * 2 + a_kb);
                ldsm_x4(ahi[mf], cur + 0 * TILE_BYTES + sw(arow, ach));
                ldsm_x4(alo[mf], cur + 1 * TILE_BYTES + sw(arow, ach));
            }
            #pragma unroll
            for (int np = 0; np < 4; np++) {   // 2 n-frags per np block
                uint32_t brow = (uint32_t)(wn * 64 + np * 16 + b_r);
                uint32_t bch  = (uint32_t)(ks * 2 + b_kb);
                uint32_t th[4], tl[4];
                ldsm_x4(th, cur + 2 * TILE_BYTES + sw(brow, bch));
                ldsm_x4(tl, cur + 3 * TILE_BYTES + sw(brow, bch));
                uint32_t b0h[2] = { th[0], th[1] }, b1h[2] = { th[2], th[3] };
                uint32_t b0l[2] = { tl[0], tl[1] }, b1l[2] = { tl[2], tl[3] };
                #pragma unroll
                for (int mf = 0; mf < 4; mf++) {
                    mma_bf16(acc[mf][np * 2],     ahi[mf], b0h);
                    mma_bf16(acc[mf][np * 2 + 1], ahi[mf], b1h);
                }
                #pragma unroll
                for (int mf = 0; mf < 4; mf++) {
                    mma_bf16(acc[mf][np * 2],     ahi[mf], b0l);
                    mma_bf16(acc[mf][np * 2 + 1], ahi[mf], b1l);
                }
                #pragma unroll
                for (int mf = 0; mf < 4; mf++) {
                    mma_bf16(acc[mf][np * 2],     alo[mf], b0h);
                    mma_bf16(acc[mf][np * 2 + 1], alo[mf], b1h);
                }
            }
        }
    }
    __syncthreads();
}

// ======================= QKV fused kernel =======================
// grid (24, 32): bx 0..7 -> Q, 8..15 -> K, 16..23 -> V (transposed into V^T)
__global__ void __launch_bounds__(128, 2) qkv_kernel(
    const __nv_bfloat16* __restrict__ hhi, const __nv_bfloat16* __restrict__ hlo,
    const __nv_bfloat16* __restrict__ wqh, const __nv_bfloat16* __restrict__ wql,
    const __nv_bfloat16* __restrict__ wkh, const __nv_bfloat16* __restrict__ wkl,
    const __nv_bfloat16* __restrict__ wvh, const __nv_bfloat16* __restrict__ wvl,
    __nv_bfloat16* __restrict__ qh, __nv_bfloat16* __restrict__ ql,
    __nv_bfloat16* __restrict__ kh, __nv_bfloat16* __restrict__ kl,
    __nv_bfloat16* __restrict__ vth, __nv_bfloat16* __restrict__ vtl)
{
    extern __shared__ char smem[];
    const uint32_t sbase = smem_u32(smem);
    const int which = blockIdx.x >> 3;          // 0=Q, 1=K, 2=V
    const int bxx = blockIdx.x & 7;

    const __nv_bfloat16* Bh = (which == 0) ? wqh : (which == 1) ? wkh : wvh;
    const __nv_bfloat16* Bl = (which == 0) ? wql : (which == 1) ? wkl : wvl;

    const size_t arow0 = (size_t)blockIdx.y * 128;
    const size_t brow0 = (size_t)bxx * 128;

    float acc[4][8][4] = {};
    gemm_core(sbase, hhi, hlo, Bh, Bl, arow0, brow0, DIM, acc);

    const int wid = threadIdx.x >> 5, lid = threadIdx.x & 31;
    const int wm = wid >> 1, wn = wid & 1;
    const int rbase = (int)arow0 + wm * 64 + (lid >> 2);
    const int cbase = (int)brow0 + wn * 64 + (lid & 3) * 2;

    if (which < 2) {
        __nv_bfloat16* Chi = (which == 0) ? qh : kh;
        __nv_bfloat16* Clo = (which == 0) ? ql : kl;
        #pragma unroll
        for (int mf = 0; mf < 4; mf++)
            #pragma unroll
            for (int nf = 0; nf < 8; nf++)
                #pragma unroll
                for (int half = 0; half < 2; half++) {
                    size_t r = (size_t)(rbase + mf * 16 + half * 8);
                    size_t cc = (size_t)(cbase + nf * 8);
                    __nv_bfloat162 hv, lv;
                    split1(acc[mf][nf][half * 2],     hv.x, lv.x);
                    split1(acc[mf][nf][half * 2 + 1], hv.y, lv.y);
                    *reinterpret_cast<__nv_bfloat162*>(Chi + r * DIM + cc) = hv;
                    *reinterpret_cast<__nv_bfloat162*>(Clo + r * DIM + cc) = lv;
                }
    } else {
        // V: write transposed -> vt[c][r]
        #pragma unroll
        for (int mf = 0; mf < 4; mf++)
            #pragma unroll
            for (int nf = 0; nf < 8; nf++)
                #pragma unroll
                for (int half = 0; half < 2; half++) {
                    size_t r = (size_t)(rbase + mf * 16 + half * 8);
                    size_t c0 = (size_t)(cbase + nf * 8);
                    float v0 = acc[mf][nf][half * 2];
                    float v1 = acc[mf][nf][half * 2 + 1];
                    __nv_bfloat16 h0, l0, h1, l1;
                    split1(v0, h0, l0);
                    split1(v1, h1, l1);
                    vth[c0 * SEQ + r] = h0;       vtl[c0 * SEQ + r] = l0;
                    vth[(c0 + 1) * SEQ + r] = h1; vtl[(c0 + 1) * SEQ + r] = l1;
                }
    }
}

// ======================= generic GEMM kernels (logits / PV) =======================
// MODE: 0 = f32 store, 2 = silu(f32) store
template <int MODE>
__global__ void __launch_bounds__(128, 2) gemm_bs(
    const __nv_bfloat16* __restrict__ Ahi, const __nv_bfloat16* __restrict__ Alo,
    const __nv_bfloat16* __restrict__ Bhi, const __nv_bfloat16* __restrict__ Blo,
    int K, int ldc, float* __restrict__ Cf)
{
    extern __shared__ char smem[];
    const uint32_t sbase = smem_u32(smem);
    const size_t arow0 = (size_t)blockIdx.y * 128;
    const size_t brow0 = (size_t)blockIdx.x * 128;

    float acc[4][8][4] = {};
    gemm_core(sbase, Ahi, Alo, Bhi, Blo, arow0, brow0, K, acc);

    const int wid = threadIdx.x >> 5, lid = threadIdx.x & 31;
    const int wm = wid >> 1, wn = wid & 1;
    const int rbase = (int)arow0 + wm * 64 + (lid >> 2);
    const int cbase = (int)brow0 + wn * 64 + (lid & 3) * 2;
    #pragma unroll
    for (int mf = 0; mf < 4; mf++)
        #pragma unroll
        for (int nf = 0; nf < 8; nf++)
            #pragma unroll
            for (int half = 0; half < 2; half++) {
                size_t r = (size_t)(rbase + mf * 16 + half * 8);
                size_t cc = (size_t)(cbase + nf * 8);
                float v0 = acc[mf][nf][half * 2];
                float v1 = acc[mf][nf][half * 2 + 1];
                if (MODE == 2) {
                    v0 = fast_silu(v0);
                    v1 = fast_silu(v1);
                }
                *reinterpret_cast<float2*>(Cf + r * ldc + cc) = make_float2(v0, v1);
            }
}

// ======================= host launch =======================
extern "C" void kernel_launch(void* const* d_in, const int* in_sizes, int n_in,
                              void* d_out, int out_size)
{
    const int*   x      = (const int*)  d_in[0];
    const float* emb    = (const float*)d_in[1];
    const float* norm_w = (const float*)d_in[2];
    const float* Wq     = (const float*)d_in[3];
    const float* Wk     = (const float*)d_in[4];
    const float* Wv     = (const float*)d_in[5];
    float* out = (float*)d_out;

    __nv_bfloat16 *h_hi, *h_lo, *wq_hi, *wq_lo, *wk_hi, *wk_lo, *wv_hi, *wv_lo;
    __nv_bfloat16 *q_hi, *q_lo, *k_hi, *k_lo, *vt_hi, *vt_lo, *p_hi, *p_lo;
    float *logits;
    cudaGetSymbolAddress((void**)&h_hi, g_h_hi);   cudaGetSymbolAddress((void**)&h_lo, g_h_lo);
    cudaGetSymbolAddress((void**)&wq_hi, g_wq_hi); cudaGetSymbolAddress((void**)&wq_lo, g_wq_lo);
    cudaGetSymbolAddress((void**)&wk_hi, g_wk_hi); cudaGetSymbolAddress((void**)&wk_lo, g_wk_lo);
    cudaGetSymbolAddress((void**)&wv_hi, g_wv_hi); cudaGetSymbolAddress((void**)&wv_lo, g_wv_lo);
    cudaGetSymbolAddress((void**)&q_hi, g_q_hi);   cudaGetSymbolAddress((void**)&q_lo, g_q_lo);
    cudaGetSymbolAddress((void**)&k_hi, g_k_hi);   cudaGetSymbolAddress((void**)&k_lo, g_k_lo);
    cudaGetSymbolAddress((void**)&vt_hi, g_vt_hi); cudaGetSymbolAddress((void**)&vt_lo, g_vt_lo);
    cudaGetSymbolAddress((void**)&p_hi, g_p_hi);   cudaGetSymbolAddress((void**)&p_lo, g_p_lo);
    cudaGetSymbolAddress((void**)&logits, g_logits);

    cudaFuncSetAttribute((const void*)qkv_kernel, cudaFuncAttributeMaxDynamicSharedMemorySize, GEMM_SMEM);
    cudaFuncSetAttribute((const void*)gemm_bs<0>, cudaFuncAttributeMaxDynamicSharedMemorySize, GEMM_SMEM);
    cudaFuncSetAttribute((const void*)gemm_bs<2>, cudaFuncAttributeMaxDynamicSharedMemorySize, GEMM_SMEM);

    // 1) embed + RMSNorm -> h hi/lo
    embed_rmsnorm_kernel<<<SEQ, 256>>>(x, emb, norm_w, h_hi, h_lo);

    // 2) split all three weights in one launch
    const int W4 = DIM * DIM / 4;   // 262144 float4s per weight
    split3_kernel<<<3 * (W4 / 256), 256>>>(
        (const float4*)Wq, (const float4*)Wk, (const float4*)Wv,
        (__nv_bfloat162*)wq_hi, (__nv_bfloat162*)wq_lo,
        (__nv_bfloat162*)wk_hi, (__nv_bfloat162*)wk_lo,
        (__nv_bfloat162*)wv_hi, (__nv_bfloat162*)wv_lo, W4);

    // 3) fused QKV projections (one launch; V written transposed+split)
    qkv_kernel<<<dim3(24, SEQ / 128), 128, GEMM_SMEM>>>(
        h_hi, h_lo, wq_hi, wq_lo, wk_hi, wk_lo, wv_hi, wv_lo,
        q_hi, q_lo, k_hi, k_lo, vt_hi, vt_lo);

    // 4) logits = q @ k^T
    dim3 gattn(SEQ / 128, SEQ / 128);
    gemm_bs<0><<<gattn, 128, GEMM_SMEM>>>(q_hi, q_lo, k_hi, k_lo, DIM, SEQ, logits);

    // 5) softmax + split -> p hi/lo (FMA-pipe exp)
    softmax_split<<<SEQ, 256>>>(logits, p_hi, p_lo);

    // 6) out = silu(P @ V) = silu(P @ (V^T)^T)
    dim3 gout(DIM / 128, SEQ / 128);
    gemm_bs<2><<<gout, 128, GEMM_SMEM>>>(p_hi, p_lo, vt_hi, vt_lo, SEQ, DIM, out);
}

// round 15
// speedup vs baseline: 1.2230x; 1.1226x over previous
#include <cuda_runtime.h>
#include <cuda_bf16.h>
#include <math.h>
#include <stdint.h>

#define SEQ 4096
#define DIM 1024
#define RMS_EPS 1.1920929e-7f  // jnp.finfo(float32).eps

// ======================= device scratch (alloc-free rule) =======================
#define AL __device__ __align__(16)
AL __nv_bfloat16 g_h_hi[SEQ * DIM],  g_h_lo[SEQ * DIM];
AL __nv_bfloat16 g_wq_hi[DIM * DIM], g_wq_lo[DIM * DIM];
AL __nv_bfloat16 g_wk_hi[DIM * DIM], g_wk_lo[DIM * DIM];
AL __nv_bfloat16 g_wv_hi[DIM * DIM], g_wv_lo[DIM * DIM];
AL __nv_bfloat16 g_q_hi[SEQ * DIM],  g_q_lo[SEQ * DIM];
AL __nv_bfloat16 g_k_hi[SEQ * DIM],  g_k_lo[SEQ * DIM];
AL __nv_bfloat16 g_vt_hi[DIM * SEQ], g_vt_lo[DIM * SEQ];   // V^T [DIM, SEQ]
AL float         g_logits[(size_t)SEQ * SEQ];
AL __nv_bfloat16 g_p_hi[(size_t)SEQ * SEQ], g_p_lo[(size_t)SEQ * SEQ];

// ======================= PTX helpers (base sm_103 target — no 'a' features) ==========
__device__ __forceinline__ uint32_t smem_u32(const void* p) {
    uint32_t a;
    asm("{ .reg .u64 t; cvta.to.shared.u64 t, %1; cvt.u32.u64 %0, t; }" : "=r"(a) : "l"(p));
    return a;
}
__device__ __forceinline__ void cp16(uint32_t dst, const void* src) {
    asm volatile("cp.async.cg.shared.global [%0], [%1], 16;" :: "r"(dst), "l"(src));
}
#define CP_COMMIT() asm volatile("cp.async.commit_group;" ::: "memory")
#define CP_WAIT1()  asm volatile("cp.async.wait_group 1;" ::: "memory")

__device__ __forceinline__ void ldsm_x4(uint32_t* r, uint32_t addr) {
    asm volatile("ldmatrix.sync.aligned.m8n8.x4.shared.b16 {%0,%1,%2,%3}, [%4];"
        : "=r"(r[0]), "=r"(r[1]), "=r"(r[2]), "=r"(r[3]) : "r"(addr) : "memory");
}
__device__ __forceinline__ void mma_bf16(float* c, const uint32_t* a, const uint32_t* b) {
    asm volatile(
        "mma.sync.aligned.m16n8k16.row.col.f32.bf16.bf16.f32 "
        "{%0,%1,%2,%3}, {%4,%5,%6,%7}, {%8,%9}, {%0,%1,%2,%3};"
        : "+f"(c[0]), "+f"(c[1]), "+f"(c[2]), "+f"(c[3])
        : "r"(a[0]), "r"(a[1]), "r"(a[2]), "r"(a[3]), "r"(b[0]), "r"(b[1]));
}

// ======================= fast math (FMA-pipe, no MUFU) =======================
__device__ __forceinline__ float fast_exp(float x) {
    float t = x * 1.4426950408889634f;
    t = fmaxf(fminf(t, 125.0f), -125.0f);
    float r = t + 12582912.0f;                       // 2^23 + 2^22 (round to nearest int)
    int   n = __float_as_int(r) - 0x4B400000;
    float f = t - (r - 12582912.0f);                 // f in [-0.5, 0.5]
    float p = 1.5403530393381609e-4f;
    p = fmaf(p, f, 1.3333558146428443e-3f);
    p = fmaf(p, f, 9.6181291076284772e-3f);
    p = fmaf(p, f, 5.5504108664821580e-2f);
    p = fmaf(p, f, 2.4022650695910072e-1f);
    p = fmaf(p, f, 6.9314718055994531e-1f);
    p = fmaf(p, f, 1.0f);
    return __int_as_float(__float_as_int(p) + (n << 23));
}
__device__ __forceinline__ float fast_rcp(float y) {
    float r = __int_as_float(0x7EF311C3 - __float_as_int(y));
    r = r * (2.0f - y * r);
    r = r * (2.0f - y * r);
    r = r * (2.0f - y * r);
    return r;
}
__device__ __forceinline__ float fast_silu(float v) {
    float e = fast_exp(-v);
    return v * fast_rcp(1.0f + e);
}

// ======================= split helper =======================
__device__ __forceinline__ void split1(float a, __nv_bfloat16& hi, __nv_bfloat16& lo) {
    hi = __float2bfloat16(a);
    lo = __float2bfloat16(a - __bfloat162float(hi));
}

// ======================= block reductions =======================
__device__ __forceinline__ float block_reduce_sum(float val) {
    __shared__ float sh[32];
    __syncthreads();
    int lane = threadIdx.x & 31, wid = threadIdx.x >> 5;
    #pragma unroll
    for (int o = 16; o > 0; o >>= 1) val += __shfl_down_sync(0xffffffffu, val, o);
    if (lane == 0) sh[wid] = val;
    __syncthreads();
    int nw = (blockDim.x + 31) >> 5;
    val = (threadIdx.x < nw) ? sh[threadIdx.x] : 0.0f;
    if (wid == 0) {
        #pragma unroll
        for (int o = 16; o > 0; o >>= 1) val += __shfl_down_sync(0xffffffffu, val, o);
        if (lane == 0) sh[0] = val;
    }
    __syncthreads();
    return sh[0];
}
__device__ __forceinline__ float block_reduce_max(float val) {
    __shared__ float sh[32];
    __syncthreads();
    int lane = threadIdx.x & 31, wid = threadIdx.x >> 5;
    #pragma unroll
    for (int o = 16; o > 0; o >>= 1) val = fmaxf(val, __shfl_down_sync(0xffffffffu, val, o));
    if (lane == 0) sh[wid] = val;
    __syncthreads();
    int nw = (blockDim.x + 31) >> 5;
    val = (threadIdx.x < nw) ? sh[threadIdx.x] : -INFINITY;
    if (wid == 0) {
        #pragma unroll
        for (int o = 16; o > 0; o >>= 1) val = fmaxf(val, __shfl_down_sync(0xffffffffu, val, o));
        if (lane == 0) sh[0] = val;
    }
    __syncthreads();
    return sh[0];
}

// ======================= embed + RMSNorm -> bf16 hi/lo =======================
__global__ void __launch_bounds__(256) embed_rmsnorm_kernel(
    const int* __restrict__ x, const float* __restrict__ emb,
    const float* __restrict__ norm_w,
    __nv_bfloat16* __restrict__ hhi, __nv_bfloat16* __restrict__ hlo)
{
    int s = blockIdx.x;
    int row = x[s];
    const float4* e4 = reinterpret_cast<const float4*>(emb + (size_t)row * DIM);
    const float4* w4 = reinterpret_cast<const float4*>(norm_w);

    float4 v = e4[threadIdx.x];
    float ss = v.x * v.x + v.y * v.y + v.z * v.z + v.w * v.w;
    ss = block_reduce_sum(ss);
    float scale = rsqrtf(ss * (1.0f / DIM) + RMS_EPS);
    float4 w = w4[threadIdx.x];
    float o[4];
    o[0] = v.x * scale * w.x; o[1] = v.y * scale * w.y;
    o[2] = v.z * scale * w.z; o[3] = v.w * scale * w.w;

    __nv_bfloat162* ph = reinterpret_cast<__nv_bfloat162*>(hhi + (size_t)s * DIM);
    __nv_bfloat162* pl = reinterpret_cast<__nv_bfloat162*>(hlo + (size_t)s * DIM);
    #pragma unroll
    for (int i = 0; i < 2; i++) {
        __nv_bfloat162 h2, l2;
        split1(o[2 * i],     h2.x, l2.x);
        split1(o[2 * i + 1], h2.y, l2.y);
        ph[threadIdx.x * 2 + i] = h2;
        pl[threadIdx.x * 2 + i] = l2;
    }
}

// ======================= f32 -> bf16 hi/lo: all three weights in one launch ============
__global__ void __launch_bounds__(256) split3_kernel(
    const float4* __restrict__ sa, const float4* __restrict__ sb, const float4* __restrict__ sc,
    __nv_bfloat162* __restrict__ ah, __nv_bfloat162* __restrict__ al,
    __nv_bfloat162* __restrict__ bh, __nv_bfloat162* __restrict__ bl,
    __nv_bfloat162* __restrict__ ch, __nv_bfloat162* __restrict__ cl, int n4)
{
    int which = blockIdx.x / ((n4 + 255) / 256);
    int i = (blockIdx.x % ((n4 + 255) / 256)) * 256 + threadIdx.x;
    if (i >= n4) return;
    const float4* src = (which == 0) ? sa : (which == 1) ? sb : sc;
    __nv_bfloat162* hi = (which == 0) ? ah : (which == 1) ? bh : ch;
    __nv_bfloat162* lo = (which == 0) ? al : (which == 1) ? bl : cl;
    float4 v = src[i];
    __nv_bfloat162 h0, l0, h1, l1;
    split1(v.x, h0.x, l0.x); split1(v.y, h0.y, l0.y);
    split1(v.z, h1.x, l1.x); split1(v.w, h1.y, l1.y);
    hi[2 * i] = h0; hi[2 * i + 1] = h1;
    lo[2 * i] = l0; lo[2 * i + 1] = l1;
}

// ======================= softmax rows + split to bf16 hi/lo (FMA-pipe exp) ==========
__global__ void __launch_bounds__(256) softmax_split(
    const float* __restrict__ logits,
    __nv_bfloat16* __restrict__ phi, __nv_bfloat16* __restrict__ plo)
{
    const float4* row = reinterpret_cast<const float4*>(logits + (size_t)blockIdx.x * SEQ);
    float4 v[4];
    float mx = -INFINITY;
    #pragma unroll
    for (int i = 0; i < 4; i++) {
        v[i] = row[threadIdx.x + i * 256];
        mx = fmaxf(mx, fmaxf(fmaxf(v[i].x, v[i].y), fmaxf(v[i].z, v[i].w)));
    }
    mx = block_reduce_max(mx);
    float sum = 0.0f;
    #pragma unroll
    for (int i = 0; i < 4; i++) {
        v[i].x = fast_exp(v[i].x - mx); v[i].y = fast_exp(v[i].y - mx);
        v[i].z = fast_exp(v[i].z - mx); v[i].w = fast_exp(v[i].w - mx);
        sum += v[i].x + v[i].y + v[i].z + v[i].w;
    }
    sum = block_reduce_sum(sum);
    float inv = fast_rcp(sum);
    __nv_bfloat162* ph = reinterpret_cast<__nv_bfloat162*>(phi + (size_t)blockIdx.x * SEQ);
    __nv_bfloat162* pl = reinterpret_cast<__nv_bfloat162*>(plo + (size_t)blockIdx.x * SEQ);
    #pragma unroll
    for (int i = 0; i < 4; i++) {
        __nv_bfloat162 h0, l0, h1, l1;
        split1(v[i].x * inv, h0.x, l0.x); split1(v[i].y * inv, h0.y, l0.y);
        split1(v[i].z * inv, h1.x, l1.x); split1(v[i].w * inv, h1.y, l1.y);
        int f = threadIdx.x + i * 256;
        ph[2 * f] = h0; ph[2 * f + 1] = h1;
        pl[2 * f] = l0; pl[2 * f + 1] = l1;
    }
}

// ======================= shared GEMM core (mma.sync bf16-split) =======================
// 128x128 CTA tile, 128 threads, 4 warps in 2x2, warp tile 64x64, 3-stage pipeline.
// R10: next-stage cp.async issued BETWEEN ks=0 and ks=1 so the LDGSTS burst hides
// behind the tensor pipe instead of stalling the chunk front.
#define TILE_BYTES 8192              // 128 rows x 64B (32 bf16)
#define STAGE_BYTES (4 * TILE_BYTES) // Ahi, Alo, Bhi, Blo
#define NSTAGE 3
#define GEMM_SMEM (NSTAGE * STAGE_BYTES)

__device__ __forceinline__ uint32_t sw(uint32_t row, uint32_t chunk) {
    return row * 64u + ((chunk ^ ((row >> 1) & 3u)) << 4);
}

__device__ __forceinline__ void load_stage(uint32_t sbase,
    const __nv_bfloat16* __restrict__ Ahi, const __nv_bfloat16* __restrict__ Alo,
    const __nv_bfloat16* __restrict__ Bhi, const __nv_bfloat16* __restrict__ Blo,
    size_t arow0, size_t brow0, int K, int k0, int tid)
{
    #pragma unroll
    for (int j = 0; j < 4; j++) {
        int idx = tid + j * 128;
        int row = idx >> 2, ch = idx & 3;
        uint32_t so = sw(row, ch);
        size_t goff = (size_t)row * K + k0 + ch * 8;   // bf16 elements
        cp16(sbase + 0 * TILE_BYTES + so, Ahi + arow0 * K + goff);
        cp16(sbase + 1 * TILE_BYTES + so, Alo + arow0 * K + goff);
        cp16(sbase + 2 * TILE_BYTES + so, Bhi + brow0 * K + goff);
        cp16(sbase + 3 * TILE_BYTES + so, Blo + brow0 * K + goff);
    }
}

__device__ __forceinline__ void gemm_core(uint32_t sbase,
    const __nv_bfloat16* __restrict__ Ahi, const __nv_bfloat16* __restrict__ Alo,
    const __nv_bfloat16* __restrict__ Bhi, const __nv_bfloat16* __restrict__ Blo,
    size_t arow0, size_t brow0, int K, float acc[4][8][4])
{
    const int tid = threadIdx.x, wid = tid >> 5, lid = tid & 31;
    const int wm = wid >> 1, wn = wid & 1;      // 2 x 2 warp grid, warp tile 64x64

    const int a_r  = (lid & 7) + ((lid >> 3) & 1) * 8;
    const int a_kb = lid >> 4;
    const int b_r  = (lid & 7) + (lid >> 4) * 8;
    const int b_kb = (lid >> 3) & 1;
    const int nch = K >> 5;

    load_stage(sbase, Ahi, Alo, Bhi, Blo, arow0, brow0, K, 0, tid);
    CP_COMMIT();
    load_stage(sbase + STAGE_BYTES, Ahi, Alo, Bhi, Blo, arow0, brow0, K, 32, tid);
    CP_COMMIT();

    int slot = 0, nslot = 2;
    for (int c = 0; c < nch; c++) {
        CP_WAIT1();
        __syncthreads();
        const uint32_t cur = sbase + (uint32_t)slot * STAGE_BYTES;

        #pragma unroll
        for (int ks = 0; ks < 2; ks++) {
            uint32_t ahi[4][4], alo[4][4];
            #pragma unroll
            for (int mf = 0; mf < 4; mf++) {
                uint32_t arow = (uint32_t)(wm * 64 + mf * 16 + a_r);
                uint32_t ach  = (uint32_t)(ks * 2 + a_kb);
                ldsm_x4(ahi[mf], cur + 0 * TILE_BYTES + sw(arow, ach));
                ldsm_x4(alo[mf], cur + 1 * TILE_BYTES + sw(arow, ach));
            }
            #pragma unroll
            for (int np = 0; np < 4; np++) {   // 2 n-frags per np block
                uint32_t brow = (uint32_t)(wn * 64 + np * 16 + b_r);
                uint32_t bch  = (uint32_t)(ks * 2 + b_kb);
                uint32_t th[4], tl[4];
                ldsm_x4(th, cur + 2 * TILE_BYTES + sw(brow, bch));
                ldsm_x4(tl, cur + 3 * TILE_BYTES + sw(brow, bch));
                uint32_t b0h[2] = { th[0], th[1] }, b1h[2] = { th[2], th[3] };
                uint32_t b0l[2] = { tl[0], tl[1] }, b1l[2] = { tl[2], tl[3] };
                #pragma unroll
                for (int mf = 0; mf < 4; mf++) {
                    mma_bf16(acc[mf][np * 2],     ahi[mf], b0h);
                    mma_bf16(acc[mf][np * 2 + 1], ahi[mf], b1h);
                }
                #pragma unroll
                for (int mf = 0; mf < 4; mf++) {
                    mma_bf16(acc[mf][np * 2],     ahi[mf], b0l);
                    mma_bf16(acc[mf][np * 2 + 1], ahi[mf], b1l);
                }
                #pragma unroll
                for (int mf = 0; mf < 4; mf++) {
                    mma_bf16(acc[mf][np * 2],     alo[mf], b0h);
                    mma_bf16(acc[mf][np * 2 + 1], alo[mf], b1h);
                }
            }
            // R10: issue the next-stage global->smem copies in the middle of the
            // chunk (after ks=0's MMA backlog is queued) so the LDGSTS issue burst
            // overlaps tensor-pipe execution instead of stalling the chunk front.
            if (ks == 0) {
                if (c + 2 < nch)
                    load_stage(sbase + (uint32_t)nslot * STAGE_BYTES,
                               Ahi, Alo, Bhi, Blo, arow0, brow0, K, (c + 2) * 32, tid);
                CP_COMMIT();   // always commit to keep wait_group 1 semantics
            }
        }
        slot = (slot == 2) ? 0 : slot + 1;
        nslot = (nslot == 2) ? 0 : nslot + 1;
    }
    __syncthreads();
}

// ======================= QKV fused kernel =======================
// grid (24, 32): bx 0..7 -> Q, 8..15 -> K, 16..23 -> V (transposed into V^T)
__global__ void __launch_bounds__(128, 2) qkv_kernel(
    const __nv_bfloat16* __restrict__ hhi, const __nv_bfloat16* __restrict__ hlo,
    const __nv_bfloat16* __restrict__ wqh, const __nv_bfloat16* __restrict__ wql,
    const __nv_bfloat16* __restrict__ wkh, const __nv_bfloat16* __restrict__ wkl,
    const __nv_bfloat16* __restrict__ wvh, const __nv_bfloat16* __restrict__ wvl,
    __nv_bfloat16* __restrict__ qh, __nv_bfloat16* __restrict__ ql,
    __nv_bfloat16* __restrict__ kh, __nv_bfloat16* __restrict__ kl,
    __nv_bfloat16* __restrict__ vth, __nv_bfloat16* __restrict__ vtl)
{
    extern __shared__ char smem[];
    const uint32_t sbase = smem_u32(smem);
    const int which = blockIdx.x >> 3;          // 0=Q, 1=K, 2=V
    const int bxx = blockIdx.x & 7;

    const __nv_bfloat16* Bh = (which == 0) ? wqh : (which == 1) ? wkh : wvh;
    const __nv_bfloat16* Bl = (which == 0) ? wql : (which == 1) ? wkl : wvl;

    const size_t arow0 = (size_t)blockIdx.y * 128;
    const size_t brow0 = (size_t)bxx * 128;

    float acc[4][8][4] = {};
    gemm_core(sbase, hhi, hlo, Bh, Bl, arow0, brow0, DIM, acc);

    const int wid = threadIdx.x >> 5, lid = threadIdx.x & 31;
    const int wm = wid >> 1, wn = wid & 1;
    const int rbase = (int)arow0 + wm * 64 + (lid >> 2);
    const int cbase = (int)brow0 + wn * 64 + (lid & 3) * 2;

    if (which < 2) {
        __nv_bfloat16* Chi = (which == 0) ? qh : kh;
        __nv_bfloat16* Clo = (which == 0) ? ql : kl;
        #pragma unroll
        for (int mf = 0; mf < 4; mf++)
            #pragma unroll
            for (int nf = 0; nf < 8; nf++)
                #pragma unroll
                for (int half = 0; half < 2; half++) {
                    size_t r = (size_t)(rbase + mf * 16 + half * 8);
                    size_t cc = (size_t)(cbase + nf * 8);
                    __nv_bfloat162 hv, lv;
                    split1(acc[mf][nf][half * 2],     hv.x, lv.x);
                    split1(acc[mf][nf][half * 2 + 1], hv.y, lv.y);
                    *reinterpret_cast<__nv_bfloat162*>(Chi + r * DIM + cc) = hv;
                    *reinterpret_cast<__nv_bfloat162*>(Clo + r * DIM + cc) = lv;
                }
    } else {
        // V: write transposed -> vt[c][r]
        #pragma unroll
        for (int mf = 0; mf < 4; mf++)
            #pragma unroll
            for (int nf = 0; nf < 8; nf++)
                #pragma unroll
                for (int half = 0; half < 2; half++) {
                    size_t r = (size_t)(rbase + mf * 16 + half * 8);
                    size_t c0 = (size_t)(cbase + nf * 8);
                    float v0 = acc[mf][nf][half * 2];
                    float v1 = acc[mf][nf][half * 2 + 1];
                    __nv_bfloat16 h0, l0, h1, l1;
                    split1(v0, h0, l0);
                    split1(v1, h1, l1);
                    vth[c0 * SEQ + r] = h0;       vtl[c0 * SEQ + r] = l0;
                    vth[(c0 + 1) * SEQ + r] = h1; vtl[(c0 + 1) * SEQ + r] = l1;
                }
    }
}

// ======================= generic GEMM kernels (logits / PV) =======================
// MODE: 0 = f32 store, 2 = silu(f32) store
template <int MODE>
__global__ void __launch_bounds__(128, 2) gemm_bs(
    const __nv_bfloat16* __restrict__ Ahi, const __nv_bfloat16* __restrict__ Alo,
    const __nv_bfloat16* __restrict__ Bhi, const __nv_bfloat16* __restrict__ Blo,
    int K, int ldc, float* __restrict__ Cf)
{
    extern __shared__ char smem[];
    const uint32_t sbase = smem_u32(smem);
    const size_t arow0 = (size_t)blockIdx.y * 128;
    const size_t brow0 = (size_t)blockIdx.x * 128;

    float acc[4][8][4] = {};
    gemm_core(sbase, Ahi, Alo, Bhi, Blo, arow0, brow0, K, acc);

    const int wid = threadIdx.x >> 5, lid = threadIdx.x & 31;
    const int wm = wid >> 1, wn = wid & 1;
    const int rbase = (int)arow0 + wm * 64 + (lid >> 2);
    const int cbase = (int)brow0 + wn * 64 + (lid & 3) * 2;
    #pragma unroll
    for (int mf = 0; mf < 4; mf++)
        #pragma unroll
        for (int nf = 0; nf < 8; nf++)
            #pragma unroll
            for (int half = 0; half < 2; half++) {
                size_t r = (size_t)(rbase + mf * 16 + half * 8);
                size_t cc = (size_t)(cbase + nf * 8);
                float v0 = acc[mf][nf][half * 2];
                float v1 = acc[mf][nf][half * 2 + 1];
                if (MODE == 2) {
                    v0 = fast_silu(v0);
                    v1 = fast_silu(v1);
                }
                *reinterpret_cast<float2*>(Cf + r * ldc + cc) = make_float2(v0, v1);
            }
}

// ======================= host launch =======================
extern "C" void kernel_launch(void* const* d_in, const int* in_sizes, int n_in,
                              void* d_out, int out_size)
{
    const int*   x      = (const int*)  d_in[0];
    const float* emb    = (const float*)d_in[1];
    const float* norm_w = (const float*)d_in[2];
    const float* Wq     = (const float*)d_in[3];
    const float* Wk     = (const float*)d_in[4];
    const float* Wv     = (const float*)d_in[5];
    float* out = (float*)d_out;

    __nv_bfloat16 *h_hi, *h_lo, *wq_hi, *wq_lo, *wk_hi, *wk_lo, *wv_hi, *wv_lo;
    __nv_bfloat16 *q_hi, *q_lo, *k_hi, *k_lo, *vt_hi, *vt_lo, *p_hi, *p_lo;
    float *logits;
    cudaGetSymbolAddress((void**)&h_hi, g_h_hi);   cudaGetSymbolAddress((void**)&h_lo, g_h_lo);
    cudaGetSymbolAddress((void**)&wq_hi, g_wq_hi); cudaGetSymbolAddress((void**)&wq_lo, g_wq_lo);
    cudaGetSymbolAddress((void**)&wk_hi, g_wk_hi); cudaGetSymbolAddress((void**)&wk_lo, g_wk_lo);
    cudaGetSymbolAddress((void**)&wv_hi, g_wv_hi); cudaGetSymbolAddress((void**)&wv_lo, g_wv_lo);
    cudaGetSymbolAddress((void**)&q_hi, g_q_hi);   cudaGetSymbolAddress((void**)&q_lo, g_q_lo);
    cudaGetSymbolAddress((void**)&k_hi, g_k_hi);   cudaGetSymbolAddress((void**)&k_lo, g_k_lo);
    cudaGetSymbolAddress((void**)&vt_hi, g_vt_hi); cudaGetSymbolAddress((void**)&vt_lo, g_vt_lo);
    cudaGetSymbolAddress((void**)&p_hi, g_p_hi);   cudaGetSymbolAddress((void**)&p_lo, g_p_lo);
    cudaGetSymbolAddress((void**)&logits, g_logits);

    cudaFuncSetAttribute((const void*)qkv_kernel, cudaFuncAttributeMaxDynamicSharedMemorySize, GEMM_SMEM);
    cudaFuncSetAttribute((const void*)gemm_bs<0>, cudaFuncAttributeMaxDynamicSharedMemorySize, GEMM_SMEM);
    cudaFuncSetAttribute((const void*)gemm_bs<2>, cudaFuncAttributeMaxDynamicSharedMemorySize, GEMM_SMEM);

    // 1) embed + RMSNorm -> h hi/lo
    embed_rmsnorm_kernel<<<SEQ, 256>>>(x, emb, norm_w, h_hi, h_lo);

    // 2) split all three weights in one launch
    const int W4 = DIM * DIM / 4;   // 262144 float4s per weight
    split3_kernel<<<3 * (W4 / 256), 256>>>(
        (const float4*)Wq, (const float4*)Wk, (const float4*)Wv,
        (__nv_bfloat162*)wq_hi, (__nv_bfloat162*)wq_lo,
        (__nv_bfloat162*)wk_hi, (__nv_bfloat162*)wk_lo,
        (__nv_bfloat162*)wv_hi, (__nv_bfloat162*)wv_lo, W4);

    // 3) fused QKV projections (one launch; V written transposed+split)
    qkv_kernel<<<dim3(24, SEQ / 128), 128, GEMM_SMEM>>>(
        h_hi, h_lo, wq_hi, wq_lo, wk_hi, wk_lo, wv_hi, wv_lo,
        q_hi, q_lo, k_hi, k_lo, vt_hi, vt_lo);

    // 4) logits = q @ k^T
    dim3 gattn(SEQ / 128, SEQ / 128);
    gemm_bs<0><<<gattn, 128, GEMM_SMEM>>>(q_hi, q_lo, k_hi, k_lo, DIM, SEQ, logits);

    // 5) softmax + split -> p hi/lo (FMA-pipe exp)
    softmax_split<<<SEQ, 256>>>(logits, p_hi, p_lo);

    // 6) out = silu(P @ V) = silu(P @ (V^T)^T)
    dim3 gout(DIM / 128, SEQ / 128);
    gemm_bs<2><<<gout, 128, GEMM_SMEM>>>(p_hi, p_lo, vt_hi, vt_lo, SEQ, DIM, out);
}

// round 16
// speedup vs baseline: 1.2256x; 1.0021x over previous
#include <cuda_runtime.h>
#include <cuda_bf16.h>
#include <math.h>
#include <stdint.h>

#define SEQ 4096
#define DIM 1024
#define RMS_EPS 1.1920929e-7f  // jnp.finfo(float32).eps

// ======================= device scratch (alloc-free rule) =======================
#define AL __device__ __align__(16)
AL __nv_bfloat16 g_h_hi[SEQ * DIM],  g_h_lo[SEQ * DIM];
AL __nv_bfloat16 g_wq_hi[DIM * DIM], g_wq_lo[DIM * DIM];
AL __nv_bfloat16 g_wk_hi[DIM * DIM], g_wk_lo[DIM * DIM];
AL __nv_bfloat16 g_wv_hi[DIM * DIM], g_wv_lo[DIM * DIM];
AL __nv_bfloat16 g_q_hi[SEQ * DIM],  g_q_lo[SEQ * DIM];
AL __nv_bfloat16 g_k_hi[SEQ * DIM],  g_k_lo[SEQ * DIM];
AL __nv_bfloat16 g_vt_hi[DIM * SEQ], g_vt_lo[DIM * SEQ];   // V^T [DIM, SEQ]
AL float         g_logits[(size_t)SEQ * SEQ];
AL __nv_bfloat16 g_p_hi[(size_t)SEQ * SEQ], g_p_lo[(size_t)SEQ * SEQ];

// ======================= PTX helpers (base sm_103 target — no 'a' features) ==========
__device__ __forceinline__ uint32_t smem_u32(const void* p) {
    uint32_t a;
    asm("{ .reg .u64 t; cvta.to.shared.u64 t, %1; cvt.u32.u64 %0, t; }" : "=r"(a) : "l"(p));
    return a;
}
__device__ __forceinline__ void cp16(uint32_t dst, const void* src) {
    asm volatile("cp.async.cg.shared.global [%0], [%1], 16;" :: "r"(dst), "l"(src));
}
#define CP_COMMIT() asm volatile("cp.async.commit_group;" ::: "memory")
#define CP_WAIT1()  asm volatile("cp.async.wait_group 1;" ::: "memory")

__device__ __forceinline__ void ldsm_x4(uint32_t* r, uint32_t addr) {
    asm volatile("ldmatrix.sync.aligned.m8n8.x4.shared.b16 {%0,%1,%2,%3}, [%4];"
        : "=r"(r[0]), "=r"(r[1]), "=r"(r[2]), "=r"(r[3]) : "r"(addr) : "memory");
}
__device__ __forceinline__ void mma_bf16(float* c, const uint32_t* a, const uint32_t* b) {
    asm volatile(
        "mma.sync.aligned.m16n8k16.row.col.f32.bf16.bf16.f32 "
        "{%0,%1,%2,%3}, {%4,%5,%6,%7}, {%8,%9}, {%0,%1,%2,%3};"
        : "+f"(c[0]), "+f"(c[1]), "+f"(c[2]), "+f"(c[3])
        : "r"(a[0]), "r"(a[1]), "r"(a[2]), "r"(a[3]), "r"(b[0]), "r"(b[1]));
}

// ======================= fast math (FMA-pipe, no MUFU) =======================
__device__ __forceinline__ float fast_exp(float x) {
    float t = x * 1.4426950408889634f;
    t = fmaxf(fminf(t, 125.0f), -125.0f);
    float r = t + 12582912.0f;                       // 2^23 + 2^22 (round to nearest int)
    int   n = __float_as_int(r) - 0x4B400000;
    float f = t - (r - 12582912.0f);                 // f in [-0.5, 0.5]
    float p = 1.5403530393381609e-4f;
    p = fmaf(p, f, 1.3333558146428443e-3f);
    p = fmaf(p, f, 9.6181291076284772e-3f);
    p = fmaf(p, f, 5.5504108664821580e-2f);
    p = fmaf(p, f, 2.4022650695910072e-1f);
    p = fmaf(p, f, 6.9314718055994531e-1f);
    p = fmaf(p, f, 1.0f);
    return __int_as_float(__float_as_int(p) + (n << 23));
}
__device__ __forceinline__ float fast_rcp(float y) {
    float r = __int_as_float(0x7EF311C3 - __float_as_int(y));
    r = r * (2.0f - y * r);
    r = r * (2.0f - y * r);
    r = r * (2.0f - y * r);
    return r;
}
__device__ __forceinline__ float fast_silu(float v) {
    float e = fast_exp(-v);
    return v * fast_rcp(1.0f + e);
}

// ======================= split helper =======================
__device__ __forceinline__ void split1(float a, __nv_bfloat16& hi, __nv_bfloat16& lo) {
    hi = __float2bfloat16(a);
    lo = __float2bfloat16(a - __bfloat162float(hi));
}

// ======================= block reductions =======================
__device__ __forceinline__ float block_reduce_sum(float val) {
    __shared__ float sh[32];
    __syncthreads();
    int lane = threadIdx.x & 31, wid = threadIdx.x >> 5;
    #pragma unroll
    for (int o = 16; o > 0; o >>= 1) val += __shfl_down_sync(0xffffffffu, val, o);
    if (lane == 0) sh[wid] = val;
    __syncthreads();
    int nw = (blockDim.x + 31) >> 5;
    val = (threadIdx.x < nw) ? sh[threadIdx.x] : 0.0f;
    if (wid == 0) {
        #pragma unroll
        for (int o = 16; o > 0; o >>= 1) val += __shfl_down_sync(0xffffffffu, val, o);
        if (lane == 0) sh[0] = val;
    }
    __syncthreads();
    return sh[0];
}
__device__ __forceinline__ float block_reduce_max(float val) {
    __shared__ float sh[32];
    __syncthreads();
    int lane = threadIdx.x & 31, wid = threadIdx.x >> 5;
    #pragma unroll
    for (int o = 16; o > 0; o >>= 1) val = fmaxf(val, __shfl_down_sync(0xffffffffu, val, o));
    if (lane == 0) sh[wid] = val;
    __syncthreads();
    int nw = (blockDim.x + 31) >> 5;
    val = (threadIdx.x < nw) ? sh[threadIdx.x] : -INFINITY;
    if (wid == 0) {
        #pragma unroll
        for (int o = 16; o > 0; o >>= 1) val = fmaxf(val, __shfl_down_sync(0xffffffffu, val, o));
        if (lane == 0) sh[0] = val;
    }
    __syncthreads();
    return sh[0];
}

// ======================= fused prep: embed+RMSNorm AND weight splits ==============
// blocks [0, SEQ): embed+rmsnorm token rows. blocks [SEQ, SEQ+3*1024): weight split.
#define WBLK (DIM * DIM / 4 / 256)   // 1024 blocks per weight
__global__ void __launch_bounds__(256) prep_kernel(
    const int* __restrict__ x, const float* __restrict__ emb,
    const float* __restrict__ norm_w,
    __nv_bfloat16* __restrict__ hhi, __nv_bfloat16* __restrict__ hlo,
    const float4* __restrict__ Wq, const float4* __restrict__ Wk, const float4* __restrict__ Wv,
    __nv_bfloat162* __restrict__ ah, __nv_bfloat162* __restrict__ al,
    __nv_bfloat162* __restrict__ bh, __nv_bfloat162* __restrict__ bl,
    __nv_bfloat162* __restrict__ ch, __nv_bfloat162* __restrict__ cl)
{
    if (blockIdx.x < SEQ) {
        int s = blockIdx.x;
        int row = x[s];
        const float4* e4 = reinterpret_cast<const float4*>(emb + (size_t)row * DIM);
        const float4* w4 = reinterpret_cast<const float4*>(norm_w);

        float4 v = e4[threadIdx.x];
        float ss = v.x * v.x + v.y * v.y + v.z * v.z + v.w * v.w;
        ss = block_reduce_sum(ss);
        float scale = rsqrtf(ss * (1.0f / DIM) + RMS_EPS);
        float4 w = w4[threadIdx.x];
        float o[4];
        o[0] = v.x * scale * w.x; o[1] = v.y * scale * w.y;
        o[2] = v.z * scale * w.z; o[3] = v.w * scale * w.w;

        __nv_bfloat162* ph = reinterpret_cast<__nv_bfloat162*>(hhi + (size_t)s * DIM);
        __nv_bfloat162* pl = reinterpret_cast<__nv_bfloat162*>(hlo + (size_t)s * DIM);
        #pragma unroll
        for (int i = 0; i < 2; i++) {
            __nv_bfloat162 h2, l2;
            split1(o[2 * i],     h2.x, l2.x);
            split1(o[2 * i + 1], h2.y, l2.y);
            ph[threadIdx.x * 2 + i] = h2;
            pl[threadIdx.x * 2 + i] = l2;
        }
    } else {
        int b = blockIdx.x - SEQ;
        int which = b / WBLK;
        int i = (b % WBLK) * 256 + threadIdx.x;
        const float4* src = (which == 0) ? Wq : (which == 1) ? Wk : Wv;
        __nv_bfloat162* hi = (which == 0) ? ah : (which == 1) ? bh : ch;
        __nv_bfloat162* lo = (which == 0) ? al : (which == 1) ? bl : cl;
        float4 v = src[i];
        __nv_bfloat162 h0, l0, h1, l1;
        split1(v.x, h0.x, l0.x); split1(v.y, h0.y, l0.y);
        split1(v.z, h1.x, l1.x); split1(v.w, h1.y, l1.y);
        hi[2 * i] = h0; hi[2 * i + 1] = h1;
        lo[2 * i] = l0; lo[2 * i + 1] = l1;
    }
}

// ======================= softmax rows + split to bf16 hi/lo (packed 8B stores) =======
__global__ void __launch_bounds__(256) softmax_split(
    const float* __restrict__ logits,
    __nv_bfloat16* __restrict__ phi, __nv_bfloat16* __restrict__ plo)
{
    const float4* row = reinterpret_cast<const float4*>(logits + (size_t)blockIdx.x * SEQ);
    float4 v[4];
    float mx = -INFINITY;
    #pragma unroll
    for (int i = 0; i < 4; i++) {
        v[i] = row[threadIdx.x + i * 256];
        mx = fmaxf(mx, fmaxf(fmaxf(v[i].x, v[i].y), fmaxf(v[i].z, v[i].w)));
    }
    mx = block_reduce_max(mx);
    float sum = 0.0f;
    #pragma unroll
    for (int i = 0; i < 4; i++) {
        v[i].x = fast_exp(v[i].x - mx); v[i].y = fast_exp(v[i].y - mx);
        v[i].z = fast_exp(v[i].z - mx); v[i].w = fast_exp(v[i].w - mx);
        sum += v[i].x + v[i].y + v[i].z + v[i].w;
    }
    sum = block_reduce_sum(sum);
    float inv = fast_rcp(sum);
    uint2* ph = reinterpret_cast<uint2*>(phi + (size_t)blockIdx.x * SEQ);
    uint2* pl = reinterpret_cast<uint2*>(plo + (size_t)blockIdx.x * SEQ);
    #pragma unroll
    for (int i = 0; i < 4; i++) {
        __nv_bfloat162 h0, l0, h1, l1;
        split1(v[i].x * inv, h0.x, l0.x); split1(v[i].y * inv, h0.y, l0.y);
        split1(v[i].z * inv, h1.x, l1.x); split1(v[i].w * inv, h1.y, l1.y);
        int f = threadIdx.x + i * 256;    // one uint2 = 4 bf16 = this float4
        uint2 hv, lv;
        hv.x = *reinterpret_cast<uint32_t*>(&h0); hv.y = *reinterpret_cast<uint32_t*>(&h1);
        lv.x = *reinterpret_cast<uint32_t*>(&l0); lv.y = *reinterpret_cast<uint32_t*>(&l1);
        ph[f] = hv;
        pl[f] = lv;
    }
}

// ======================= shared GEMM core (mma.sync bf16-split) =======================
// 128x128 CTA tile, 128 threads, 4 warps in 2x2, warp tile 64x64, 3-stage pipeline.
// R11: next-stage cp.async split in half across ks=0 and ks=1 (commit at ks=1) so the
// LDGSTS issue pressure is spread evenly under the tensor-pipe stream.
#define TILE_BYTES 8192              // 128 rows x 64B (32 bf16)
#define STAGE_BYTES (4 * TILE_BYTES) // Ahi, Alo, Bhi, Blo
#define NSTAGE 3
#define GEMM_SMEM (NSTAGE * STAGE_BYTES)

__device__ __forceinline__ uint32_t sw(uint32_t row, uint32_t chunk) {
    return row * 64u + ((chunk ^ ((row >> 1) & 3u)) << 4);
}

// half = 0 loads j=0..1, half = 1 loads j=2..3
__device__ __forceinline__ void load_stage_half(uint32_t sbase,
    const __nv_bfloat16* __restrict__ Ahi, const __nv_bfloat16* __restrict__ Alo,
    const __nv_bfloat16* __restrict__ Bhi, const __nv_bfloat16* __restrict__ Blo,
    size_t arow0, size_t brow0, int K, int k0, int tid, int half)
{
    #pragma unroll
    for (int j = 0; j < 2; j++) {
        int idx = tid + (half * 2 + j) * 128;
        int row = idx >> 2, ch = idx & 3;
        uint32_t so = sw(row, ch);
        size_t goff = (size_t)row * K + k0 + ch * 8;   // bf16 elements
        cp16(sbase + 0 * TILE_BYTES + so, Ahi + arow0 * K + goff);
        cp16(sbase + 1 * TILE_BYTES + so, Alo + arow0 * K + goff);
        cp16(sbase + 2 * TILE_BYTES + so, Bhi + brow0 * K + goff);
        cp16(sbase + 3 * TILE_BYTES + so, Blo + brow0 * K + goff);
    }
}

__device__ __forceinline__ void gemm_core(uint32_t sbase,
    const __nv_bfloat16* __restrict__ Ahi, const __nv_bfloat16* __restrict__ Alo,
    const __nv_bfloat16* __restrict__ Bhi, const __nv_bfloat16* __restrict__ Blo,
    size_t arow0, size_t brow0, int K, float acc[4][8][4])
{
    const int tid = threadIdx.x, wid = tid >> 5, lid = tid & 31;
    const int wm = wid >> 1, wn = wid & 1;      // 2 x 2 warp grid, warp tile 64x64

    const int a_r  = (lid & 7) + ((lid >> 3) & 1) * 8;
    const int a_kb = lid >> 4;
    const int b_r  = (lid & 7) + (lid >> 4) * 8;
    const int b_kb = (lid >> 3) & 1;
    const int nch = K >> 5;

    load_stage_half(sbase, Ahi, Alo, Bhi, Blo, arow0, brow0, K, 0, tid, 0);
    load_stage_half(sbase, Ahi, Alo, Bhi, Blo, arow0, brow0, K, 0, tid, 1);
    CP_COMMIT();
    load_stage_half(sbase + STAGE_BYTES, Ahi, Alo, Bhi, Blo, arow0, brow0, K, 32, tid, 0);
    load_stage_half(sbase + STAGE_BYTES, Ahi, Alo, Bhi, Blo, arow0, brow0, K, 32, tid, 1);
    CP_COMMIT();

    int slot = 0, nslot = 2;
    for (int c = 0; c < nch; c++) {
        CP_WAIT1();
        __syncthreads();
        const uint32_t cur = sbase + (uint32_t)slot * STAGE_BYTES;

        #pragma unroll
        for (int ks = 0; ks < 2; ks++) {
            uint32_t ahi[4][4], alo[4][4];
            #pragma unroll
            for (int mf = 0; mf < 4; mf++) {
                uint32_t arow = (uint32_t)(wm * 64 + mf * 16 + a_r);
                uint32_t ach  = (uint32_t)(ks * 2 + a_kb);
                ldsm_x4(ahi[mf], cur + 0 * TILE_BYTES + sw(arow, ach));
                ldsm_x4(alo[mf], cur + 1 * TILE_BYTES + sw(arow, ach));
            }
            #pragma unroll
            for (int np = 0; np < 4; np++) {   // 2 n-frags per np block
                uint32_t brow = (uint32_t)(wn * 64 + np * 16 + b_r);
                uint32_t bch  = (uint32_t)(ks * 2 + b_kb);
                uint32_t th[4], tl[4];
                ldsm_x4(th, cur + 2 * TILE_BYTES + sw(brow, bch));
                ldsm_x4(tl, cur + 3 * TILE_BYTES + sw(brow, bch));
                uint32_t b0h[2] = { th[0], th[1] }, b1h[2] = { th[2], th[3] };
                uint32_t b0l[2] = { tl[0], tl[1] }, b1l[2] = { tl[2], tl[3] };
                #pragma unroll
                for (int mf = 0; mf < 4; mf++) {
                    mma_bf16(acc[mf][np * 2],     ahi[mf], b0h);
                    mma_bf16(acc[mf][np * 2 + 1], ahi[mf], b1h);
                }
                #pragma unroll
                for (int mf = 0; mf < 4; mf++) {
                    mma_bf16(acc[mf][np * 2],     ahi[mf], b0l);
                    mma_bf16(acc[mf][np * 2 + 1], ahi[mf], b1l);
                }
                #pragma unroll
                for (int mf = 0; mf < 4; mf++) {
                    mma_bf16(acc[mf][np * 2],     alo[mf], b0h);
                    mma_bf16(acc[mf][np * 2 + 1], alo[mf], b1h);
                }
            }
            // R11: half of the next-stage copies after each ks block; single commit
            // per chunk at ks=1 (wait_group 1 accounting unchanged — stage c+1's
            // group still completes a full chunk before first use).
            if (c + 2 < nch)
                load_stage_half(sbase + (uint32_t)nslot * STAGE_BYTES,
                                Ahi, Alo, Bhi, Blo, arow0, brow0, K, (c + 2) * 32, tid, ks);
            if (ks == 1) CP_COMMIT();   // always commit once per chunk
        }
        slot = (slot == 2) ? 0 : slot + 1;
        nslot = (nslot == 2) ? 0 : nslot + 1;
    }
    __syncthreads();
}

// ======================= QKV fused kernel =======================
// grid (24, 32): bx 0..7 -> Q, 8..15 -> K, 16..23 -> V (transposed into V^T)
__global__ void __launch_bounds__(128, 2) qkv_kernel(
    const __nv_bfloat16* __restrict__ hhi, const __nv_bfloat16* __restrict__ hlo,
    const __nv_bfloat16* __restrict__ wqh, const __nv_bfloat16* __restrict__ wql,
    const __nv_bfloat16* __restrict__ wkh, const __nv_bfloat16* __restrict__ wkl,
    const __nv_bfloat16* __restrict__ wvh, const __nv_bfloat16* __restrict__ wvl,
    __nv_bfloat16* __restrict__ qh, __nv_bfloat16* __restrict__ ql,
    __nv_bfloat16* __restrict__ kh, __nv_bfloat16* __restrict__ kl,
    __nv_bfloat16* __restrict__ vth, __nv_bfloat16* __restrict__ vtl)
{
    extern __shared__ char smem[];
    const uint32_t sbase = smem_u32(smem);
    const int which = blockIdx.x >> 3;          // 0=Q, 1=K, 2=V
    const int bxx = blockIdx.x & 7;

    const __nv_bfloat16* Bh = (which == 0) ? wqh : (which == 1) ? wkh : wvh;
    const __nv_bfloat16* Bl = (which == 0) ? wql : (which == 1) ? wkl : wvl;

    const size_t arow0 = (size_t)blockIdx.y * 128;
    const size_t brow0 = (size_t)bxx * 128;

    float acc[4][8][4] = {};
    gemm_core(sbase, hhi, hlo, Bh, Bl, arow0, brow0, DIM, acc);

    const int wid = threadIdx.x >> 5, lid = threadIdx.x & 31;
    const int wm = wid >> 1, wn = wid & 1;
    const int rbase = (int)arow0 + wm * 64 + (lid >> 2);
    const int cbase = (int)brow0 + wn * 64 + (lid & 3) * 2;

    if (which < 2) {
        __nv_bfloat16* Chi = (which == 0) ? qh : kh;
        __nv_bfloat16* Clo = (which == 0) ? ql : kl;
        #pragma unroll
        for (int mf = 0; mf < 4; mf++)
            #pragma unroll
            for (int nf = 0; nf < 8; nf++)
                #pragma unroll
                for (int half = 0; half < 2; half++) {
                    size_t r = (size_t)(rbase + mf * 16 + half * 8);
                    size_t cc = (size_t)(cbase + nf * 8);
                    __nv_bfloat162 hv, lv;
                    split1(acc[mf][nf][half * 2],     hv.x, lv.x);
                    split1(acc[mf][nf][half * 2 + 1], hv.y, lv.y);
                    *reinterpret_cast<__nv_bfloat162*>(Chi + r * DIM + cc) = hv;
                    *reinterpret_cast<__nv_bfloat162*>(Clo + r * DIM + cc) = lv;
                }
    } else {
        // V: write transposed -> vt[c][r]
        #pragma unroll
        for (int mf = 0; mf < 4; mf++)
            #pragma unroll
            for (int nf = 0; nf < 8; nf++)
                #pragma unroll
                for (int half = 0; half < 2; half++) {
                    size_t r = (size_t)(rbase + mf * 16 + half * 8);
                    size_t c0 = (size_t)(cbase + nf * 8);
                    float v0 = acc[mf][nf][half * 2];
                    float v1 = acc[mf][nf][half * 2 + 1];
                    __nv_bfloat16 h0, l0, h1, l1;
                    split1(v0, h0, l0);
                    split1(v1, h1, l1);
                    vth[c0 * SEQ + r] = h0;       vtl[c0 * SEQ + r] = l0;
                    vth[(c0 + 1) * SEQ + r] = h1; vtl[(c0 + 1) * SEQ + r] = l1;
                }
    }
}

// ======================= generic GEMM kernels (logits / PV) =======================
// MODE: 0 = f32 store, 2 = silu(f32) store
template <int MODE>
__global__ void __launch_bounds__(128, 2) gemm_bs(
    const __nv_bfloat16* __restrict__ Ahi, const __nv_bfloat16* __restrict__ Alo,
    const __nv_bfloat16* __restrict__ Bhi, const __nv_bfloat16* __restrict__ Blo,
    int K, int ldc, float* __restrict__ Cf)
{
    extern __shared__ char smem[];
    const uint32_t sbase = smem_u32(smem);
    const size_t arow0 = (size_t)blockIdx.y * 128;
    const size_t brow0 = (size_t)blockIdx.x * 128;

    float acc[4][8][4] = {};
    gemm_core(sbase, Ahi, Alo, Bhi, Blo, arow0, brow0, K, acc);

    const int wid = threadIdx.x >> 5, lid = threadIdx.x & 31;
    const int wm = wid >> 1, wn = wid & 1;
    const int rbase = (int)arow0 + wm * 64 + (lid >> 2);
    const int cbase = (int)brow0 + wn * 64 + (lid & 3) * 2;
    #pragma unroll
    for (int mf = 0; mf < 4; mf++)
        #pragma unroll
        for (int nf = 0; nf < 8; nf++)
            #pragma unroll
            for (int half = 0; half < 2; half++) {
                size_t r = (size_t)(rbase + mf * 16 + half * 8);
                size_t cc = (size_t)(cbase + nf * 8);
                float v0 = acc[mf][nf][half * 2];
                float v1 = acc[mf][nf][half * 2 + 1];
                if (MODE == 2) {
                    v0 = fast_silu(v0);
                    v1 = fast_silu(v1);
                }
                *reinterpret_cast<float2*>(Cf + r * ldc + cc) = make_float2(v0, v1);
            }
}

// ======================= host launch =======================
extern "C" void kernel_launch(void* const* d_in, const int* in_sizes, int n_in,
                              void* d_out, int out_size)
{
    const int*   x      = (const int*)  d_in[0];
    const float* emb    = (const float*)d_in[1];
    const float* norm_w = (const float*)d_in[2];
    const float* Wq     = (const float*)d_in[3];
    const float* Wk     = (const float*)d_in[4];
    const float* Wv     = (const float*)d_in[5];
    float* out = (float*)d_out;

    __nv_bfloat16 *h_hi, *h_lo, *wq_hi, *wq_lo, *wk_hi, *wk_lo, *wv_hi, *wv_lo;
    __nv_bfloat16 *q_hi, *q_lo, *k_hi, *k_lo, *vt_hi, *vt_lo, *p_hi, *p_lo;
    float *logits;
    cudaGetSymbolAddress((void**)&h_hi, g_h_hi);   cudaGetSymbolAddress((void**)&h_lo, g_h_lo);
    cudaGetSymbolAddress((void**)&wq_hi, g_wq_hi); cudaGetSymbolAddress((void**)&wq_lo, g_wq_lo);
    cudaGetSymbolAddress((void**)&wk_hi, g_wk_hi); cudaGetSymbolAddress((void**)&wk_lo, g_wk_lo);
    cudaGetSymbolAddress((void**)&wv_hi, g_wv_hi); cudaGetSymbolAddress((void**)&wv_lo, g_wv_lo);
    cudaGetSymbolAddress((void**)&q_hi, g_q_hi);   cudaGetSymbolAddress((void**)&q_lo, g_q_lo);
    cudaGetSymbolAddress((void**)&k_hi, g_k_hi);   cudaGetSymbolAddress((void**)&k_lo, g_k_lo);
    cudaGetSymbolAddress((void**)&vt_hi, g_vt_hi); cudaGetSymbolAddress((void**)&vt_lo, g_vt_lo);
    cudaGetSymbolAddress((void**)&p_hi, g_p_hi);   cudaGetSymbolAddress((void**)&p_lo, g_p_lo);
    cudaGetSymbolAddress((void**)&logits, g_logits);

    cudaFuncSetAttribute((const void*)qkv_kernel, cudaFuncAttributeMaxDynamicSharedMemorySize, GEMM_SMEM);
    cudaFuncSetAttribute((const void*)gemm_bs<0>, cudaFuncAttributeMaxDynamicSharedMemorySize, GEMM_SMEM);
    cudaFuncSetAttribute((const void*)gemm_bs<2>, cudaFuncAttributeMaxDynamicSharedMemorySize, GEMM_SMEM);

    // 1) fused: embed+RMSNorm (blocks 0..4095) + weight splits (blocks 4096..7167)
    prep_kernel<<<SEQ + 3 * WBLK, 256>>>(
        x, emb, norm_w, h_hi, h_lo,
        (const float4*)Wq, (const float4*)Wk, (const float4*)Wv,
        (__nv_bfloat162*)wq_hi, (__nv_bfloat162*)wq_lo,
        (__nv_bfloat162*)wk_hi, (__nv_bfloat162*)wk_lo,
        (__nv_bfloat162*)wv_hi, (__nv_bfloat162*)wv_lo);

    // 2) fused QKV projections (one launch; V written transposed+split)
    qkv_kernel<<<dim3(24, SEQ / 128), 128, GEMM_SMEM>>>(
        h_hi, h_lo, wq_hi, wq_lo, wk_hi, wk_lo, wv_hi, wv_lo,
        q_hi, q_lo, k_hi, k_lo, vt_hi, vt_lo);

    // 3) logits = q @ k^T
    dim3 gattn(SEQ / 128, SEQ / 128);
    gemm_bs<0><<<gattn, 128, GEMM_SMEM>>>(q_hi, q_lo, k_hi, k_lo, DIM, SEQ, logits);

    // 4) softmax + split -> p hi/lo (FMA-pipe exp, packed stores)
    softmax_split<<<SEQ, 256>>>(logits, p_hi, p_lo);

    // 5) out = silu(P @ V) = silu(P @ (V^T)^T)
    dim3 gout(DIM / 128, SEQ / 128);
    gemm_bs<2><<<gout, 128, GEMM_SMEM>>>(p_hi, p_lo, vt_hi, vt_lo, SEQ, DIM, out);
}